// round 9
// baseline (speedup 1.0000x reference)
#include <cuda_runtime.h>
#include <cuda_bf16.h>
#include <cstdint>

#define B_ 4
#define N_ 2048
#define D_ 1024
#define M_TOT (B_ * N_)

typedef __nv_bfloat16 bf16;

// ---------------- static device scratch ----------------
__device__ bf16  g_xh[M_TOT * D_],  g_xl[M_TOT * D_];
__device__ bf16  g_Wh[3 * D_ * D_], g_Wl[3 * D_ * D_];      // W [d][e] row-major
__device__ bf16  g_Qh[M_TOT * D_],  g_Ql[M_TOT * D_];
__device__ bf16  g_Kh[M_TOT * D_],  g_Kl[M_TOT * D_];
__device__ bf16  g_Vh[M_TOT * D_],  g_Vl[M_TOT * D_];       // V row-major (trans-ldmatrix)
__device__ float g_S [(size_t)B_ * N_ * N_];
__device__ bf16  g_Ph[(size_t)B_ * N_ * N_], g_Pl[(size_t)B_ * N_ * N_];

// ---------------- smem: 4-stage ring, K-chunk = 32, 1 CTA/SM ----------------
static constexpr int ARR = 8192;
static constexpr int STAGE = 4 * ARR;             // Ah, Al, Bh, Bl = 32768
static constexpr int NSTAGE = 4;
static constexpr int SM_TOTAL = NSTAGE * STAGE;   // 131072

__device__ __forceinline__ uint32_t swzN(uint32_t r, uint32_t c) {   // 64B rows
    return r * 64u + (c ^ ((r & 6u) << 3));
}
__device__ __forceinline__ uint32_t swzT(uint32_t r, uint32_t c) {   // 256B rows
    return r * 256u + (c ^ ((r & 7u) << 4));
}

// ---------------- PTX helpers ----------------
__device__ __forceinline__ uint32_t smem_u32(const void* p) {
    uint32_t a;
    asm("{ .reg .u64 t; cvta.to.shared.u64 t, %1; cvt.u32.u64 %0, t; }" : "=r"(a) : "l"(p));
    return a;
}
__device__ __forceinline__ void cp16(uint32_t dst, const void* src) {
    asm volatile("cp.async.cg.shared.global [%0], [%1], 16;" :: "r"(dst), "l"(src));
}
__device__ __forceinline__ void cp_commit() { asm volatile("cp.async.commit_group;"); }
__device__ __forceinline__ void cp_wait1()  { asm volatile("cp.async.wait_group 1;"); }
__device__ __forceinline__ void cp_wait2()  { asm volatile("cp.async.wait_group 2;"); }

__device__ __forceinline__ void ldsm_x4(uint32_t r[4], uint32_t addr) {
    asm volatile("ldmatrix.sync.aligned.m8n8.x4.shared.b16 {%0,%1,%2,%3}, [%4];"
                 : "=r"(r[0]), "=r"(r[1]), "=r"(r[2]), "=r"(r[3]) : "r"(addr));
}
__device__ __forceinline__ void ldsm_x4_t(uint32_t r[4], uint32_t addr) {
    asm volatile("ldmatrix.sync.aligned.m8n8.x4.trans.shared.b16 {%0,%1,%2,%3}, [%4];"
                 : "=r"(r[0]), "=r"(r[1]), "=r"(r[2]), "=r"(r[3]) : "r"(addr));
}
__device__ __forceinline__ void mma16816(float c[4], const uint32_t a[4], uint32_t b0, uint32_t b1) {
    asm volatile("mma.sync.aligned.m16n8k16.row.col.f32.bf16.bf16.f32 "
                 "{%0,%1,%2,%3}, {%4,%5,%6,%7}, {%8,%9}, {%0,%1,%2,%3};"
                 : "+f"(c[0]), "+f"(c[1]), "+f"(c[2]), "+f"(c[3])
                 : "r"(a[0]), "r"(a[1]), "r"(a[2]), "r"(a[3]), "r"(b0), "r"(b1));
}

__device__ __forceinline__ unsigned pack2(bf16 a, bf16 b) {
    __nv_bfloat162 t(a, b);
    return *reinterpret_cast<unsigned*>(&t);
}
__device__ __forceinline__ void split1(float v, bf16& h, bf16& l) {
    h = __float2bfloat16(v);
    l = __float2bfloat16(v - __bfloat162float(h));
}

// ---------------------------------------------------------------------------
// acc(128x128) += A(128xK)*B^T, K chunks of 32, 4-stage cp.async ring,
// deep software pipeline: fragments for step t+1 (incl. next chunk's first
// fragments) are loaded while step t's MMAs issue. 1 CTA/SM, high regs.
// ---------------------------------------------------------------------------
template <bool TRANSB>
__device__ __forceinline__ void mainloop(
    const bf16* __restrict__ Ah, const bf16* __restrict__ Al, int lda,
    const bf16* __restrict__ Bh, const bf16* __restrict__ Bl, int ldb,
    int nch, char* smem, float (&acc)[2][8][4])
{
    const uint32_t su = smem_u32(smem);
    const int tid = threadIdx.x;
    const int lane = tid & 31, w = tid >> 5;
    const int m0w = (w & 3) * 32, n0w = (w >> 2) * 64;

    const int arow = tid >> 1;
    const int ac0  = (tid & 1) * 32;
    const int tkr = tid >> 4, tseg = tid & 15;

    auto load_chunk = [&](int ch, int st) {
        const int k0 = ch * 32;
        const uint32_t base = su + st * STAGE;
        const bf16* pAh = Ah + (size_t)arow * lda + k0 + (ac0 >> 1);
        const bf16* pAl = Al + (size_t)arow * lda + k0 + (ac0 >> 1);
        uint32_t d0 = base + swzN(arow, ac0);
        uint32_t d1 = base + swzN(arow, ac0 + 16);
        cp16(d0, pAh);            cp16(d1, pAh + 8);
        cp16(d0 + ARR, pAl);      cp16(d1 + ARR, pAl + 8);
        if (!TRANSB) {
            const bf16* pBh = Bh + (size_t)arow * ldb + k0 + (ac0 >> 1);
            const bf16* pBl = Bl + (size_t)arow * ldb + k0 + (ac0 >> 1);
            uint32_t e0 = base + 2 * ARR + swzN(arow, ac0);
            uint32_t e1 = base + 2 * ARR + swzN(arow, ac0 + 16);
            cp16(e0, pBh);        cp16(e1, pBh + 8);
            cp16(e0 + ARR, pBl);  cp16(e1 + ARR, pBl + 8);
        } else {
            const bf16* pBh0 = Bh + (size_t)(k0 + tkr) * ldb + tseg * 8;
            const bf16* pBl0 = Bl + (size_t)(k0 + tkr) * ldb + tseg * 8;
            const bf16* pBh1 = Bh + (size_t)(k0 + tkr + 16) * ldb + tseg * 8;
            const bf16* pBl1 = Bl + (size_t)(k0 + tkr + 16) * ldb + tseg * 8;
            uint32_t e0 = base + 2 * ARR + swzT(tkr, tseg * 16);
            uint32_t e1 = base + 2 * ARR + swzT(tkr + 16, tseg * 16);
            cp16(e0, pBh0);       cp16(e0 + ARR, pBl0);
            cp16(e1, pBh1);       cp16(e1 + ARR, pBl1);
        }
    };

    auto ldsA = [&](uint32_t base, int kk, uint32_t (&A)[2][4], uint32_t (&Alo)[2][4]) {
        const uint32_t r0 = m0w + (lane & 15);
        const uint32_t c0 = (lane >> 4) * 16 + kk * 32;
#pragma unroll
        for (int mt = 0; mt < 2; mt++) {
            uint32_t a0 = base + swzN(r0 + mt * 16, c0);
            ldsm_x4(A[mt],   a0);
            ldsm_x4(Alo[mt], a0 + ARR);
        }
    };
    auto ldsB = [&](uint32_t base, int kk, int p, uint32_t (&q)[4], uint32_t (&ql)[4]) {
        if (!TRANSB) {
            const uint32_t r0 = n0w + (lane & 7) + ((lane >> 4) << 3) + p * 16;
            const uint32_t c0 = ((lane >> 3) & 1) * 16 + kk * 32;
            uint32_t b0 = base + 2 * ARR + swzN(r0, c0);
            ldsm_x4(q,  b0);
            ldsm_x4(ql, b0 + ARR);
        } else {
            const uint32_t r0 = (lane & 15) + kk * 16;
            const uint32_t c0 = (lane >> 4) * 16 + n0w * 2 + p * 32;
            uint32_t b0 = base + 2 * ARR + swzT(r0, c0);
            ldsm_x4_t(q,  b0);
            ldsm_x4_t(ql, b0 + ARR);
        }
    };

    // preload 3 chunks into the 4-stage ring
#pragma unroll
    for (int s = 0; s < 3; s++) {
        if (s < nch) load_chunk(s, s);
        cp_commit();
    }

    // fragment buffers: A by kk parity, B by step parity
    uint32_t Af[2][2][4], Alf[2][2][4];   // [kk][mt][4]
    uint32_t Bq[2][4], Bql[2][4];         // [parity][4]

    // initial fragments for chunk 0, step 0
    cp_wait2();          // chunk 0 data complete (own thread)
    __syncthreads();     // all threads' cp for chunk 0 visible
    ldsA(su, 0, Af[0], Alf[0]);
    ldsB(su, 0, 0, Bq[0], Bql[0]);

    for (int ch = 0; ch < nch; ch++) {
        cp_wait1();          // chunks <= ch+1 complete (own thread)
        __syncthreads();     // visibility + all warps done reading stage ch-1
        if (ch + 3 < nch) load_chunk(ch + 3, (ch + 3) & 3);
        cp_commit();

        const uint32_t base  = su + (ch & 3) * STAGE;
        const uint32_t nbase = su + ((ch + 1) & 3) * STAGE;
#pragma unroll
        for (int t = 0; t < 8; t++) {
            const int kk = t >> 2, p = t & 3, pb = t & 1;
            // prefetch fragments for step t+1 (or next chunk's step 0)
            if (t < 7) {
                const int nk = (t + 1) >> 2, np = (t + 1) & 3;
                if (np == 0) ldsA(base, nk, Af[1], Alf[1]);
                ldsB(base, nk, np, Bq[pb ^ 1], Bql[pb ^ 1]);
            } else if (ch + 1 < nch) {
                ldsA(nbase, 0, Af[0], Alf[0]);
                ldsB(nbase, 0, 0, Bq[pb ^ 1], Bql[pb ^ 1]);
            }
            const int nt0 = 2 * p, nt1 = 2 * p + 1;
            const uint32_t* q  = Bq[pb];
            const uint32_t* ql = Bql[pb];
            // term-major, 4-acc round robin
            mma16816(acc[0][nt0], Af[kk][0],  q[0],  q[1]);
            mma16816(acc[1][nt0], Af[kk][1],  q[0],  q[1]);
            mma16816(acc[0][nt1], Af[kk][0],  q[2],  q[3]);
            mma16816(acc[1][nt1], Af[kk][1],  q[2],  q[3]);

            mma16816(acc[0][nt0], Af[kk][0],  ql[0], ql[1]);
            mma16816(acc[1][nt0], Af[kk][1],  ql[0], ql[1]);
            mma16816(acc[0][nt1], Af[kk][0],  ql[2], ql[3]);
            mma16816(acc[1][nt1], Af[kk][1],  ql[2], ql[3]);

            mma16816(acc[0][nt0], Alf[kk][0], q[0],  q[1]);
            mma16816(acc[1][nt0], Alf[kk][1], q[0],  q[1]);
            mma16816(acc[0][nt1], Alf[kk][0], q[2],  q[3]);
            mma16816(acc[1][nt1], Alf[kk][1], q[2],  q[3]);
        }
    }
    __syncthreads();
}

// ---------------- precompute: fp32 -> bf16 hi/lo splits ----------------
__global__ __launch_bounds__(256) void convert_x(const float* __restrict__ x)
{
    size_t idx = (size_t)(blockIdx.x * 256 + threadIdx.x) * 4;
    float4 v = *(const float4*)(x + idx);
    bf16 h[4], l[4];
    split1(v.x, h[0], l[0]); split1(v.y, h[1], l[1]);
    split1(v.z, h[2], l[2]); split1(v.w, h[3], l[3]);
    *(uint2*)(g_xh + idx) = make_uint2(pack2(h[0], h[1]), pack2(h[2], h[3]));
    *(uint2*)(g_xl + idx) = make_uint2(pack2(l[0], l[1]), pack2(l[2], l[3]));
}

__global__ __launch_bounds__(256) void convert_w(
    const float* __restrict__ Wq, const float* __restrict__ Wk, const float* __restrict__ Wv)
{
    const float* W = (blockIdx.z == 0) ? Wq : (blockIdx.z == 1) ? Wk : Wv;
    size_t base = (size_t)blockIdx.z * D_ * D_;
    size_t idx = (size_t)(blockIdx.x * 256 + threadIdx.x) * 4;
    float4 v = *(const float4*)(W + idx);
    bf16 h[4], l[4];
    split1(v.x, h[0], l[0]); split1(v.y, h[1], l[1]);
    split1(v.z, h[2], l[2]); split1(v.w, h[3], l[3]);
    *(uint2*)(g_Wh + base + idx) = make_uint2(pack2(h[0], h[1]), pack2(h[2], h[3]));
    *(uint2*)(g_Wl + base + idx) = make_uint2(pack2(l[0], l[1]), pack2(l[2], l[3]));
}

// ---------------- GEMM 1: Q/K/V = x @ W ----------------
__global__ __launch_bounds__(256) void qkv_mm()
{
    extern __shared__ char smem[];
    const int n0 = blockIdx.x * 128, m0 = blockIdx.y * 128, z = blockIdx.z;
    float acc[2][8][4] = {};

    mainloop<true>(g_xh + (size_t)m0 * D_, g_xl + (size_t)m0 * D_, D_,
                   g_Wh + (size_t)z * D_ * D_ + n0,
                   g_Wl + (size_t)z * D_ * D_ + n0, D_,
                   D_ / 32, smem, acc);

    bf16* Oh = (z == 0) ? g_Qh : (z == 1) ? g_Kh : g_Vh;
    bf16* Ol = (z == 0) ? g_Ql : (z == 1) ? g_Kl : g_Vl;
    const int lane = threadIdx.x & 31, w = threadIdx.x >> 5;
    const int m0w = (w & 3) * 32, n0w = (w >> 2) * 64;
#pragma unroll
    for (int mt = 0; mt < 2; mt++)
#pragma unroll
        for (int nt = 0; nt < 8; nt++) {
            int m = m0 + m0w + mt * 16 + (lane >> 2);
            int n = n0 + n0w + nt * 8 + (lane & 3) * 2;
            float* c = acc[mt][nt];
            bf16 h0, l0, h1, l1;
            split1(c[0], h0, l0); split1(c[1], h1, l1);
            *(unsigned*)(Oh + (size_t)m * D_ + n) = pack2(h0, h1);
            *(unsigned*)(Ol + (size_t)m * D_ + n) = pack2(l0, l1);
            split1(c[2], h0, l0); split1(c[3], h1, l1);
            *(unsigned*)(Oh + (size_t)(m + 8) * D_ + n) = pack2(h0, h1);
            *(unsigned*)(Ol + (size_t)(m + 8) * D_ + n) = pack2(l0, l1);
        }
}

// ---------------- GEMM 2: S = Q @ K^T (compact triangular grid) ----------
__global__ __launch_bounds__(256) void qk_mm()
{
    const int i = blockIdx.x, bt = blockIdx.z;
    int qt = (int)((sqrtf(8.0f * i + 1.0f) - 1.0f) * 0.5f);
    while ((qt + 1) * (qt + 2) / 2 <= i) qt++;
    while (qt * (qt + 1) / 2 > i) qt--;
    const int kt = i - qt * (qt + 1) / 2;

    extern __shared__ char smem[];
    float acc[2][8][4] = {};

    const size_t rb = (size_t)bt * N_ * D_;
    mainloop<false>(g_Qh + rb + (size_t)qt * 128 * D_, g_Ql + rb + (size_t)qt * 128 * D_, D_,
                    g_Kh + rb + (size_t)kt * 128 * D_, g_Kl + rb + (size_t)kt * 128 * D_, D_,
                    D_ / 32, smem, acc);

    float* S = g_S + (size_t)bt * N_ * N_;
    const int lane = threadIdx.x & 31, w = threadIdx.x >> 5;
    const int m0w = (w & 3) * 32, n0w = (w >> 2) * 64;
#pragma unroll
    for (int mt = 0; mt < 2; mt++)
#pragma unroll
        for (int nt = 0; nt < 8; nt++) {
            int q = qt * 128 + m0w + mt * 16 + (lane >> 2);
            int n = kt * 128 + n0w + nt * 8 + (lane & 3) * 2;
            float* c = acc[mt][nt];
            *(float2*)(S + (size_t)q * N_ + n)       = make_float2(c[0], c[1]);
            *(float2*)(S + (size_t)(q + 8) * N_ + n) = make_float2(c[2], c[3]);
        }
}

// ---------------- softmax -> P bf16 hi/lo (zero-padded to tile) ----------
__global__ __launch_bounds__(256) void softmax_k()
{
    const int row = blockIdx.x;
    const int bt = row >> 11;
    const int q  = row & (N_ - 1);
    const size_t base = (size_t)bt * N_ * N_ + (size_t)q * N_;
    const float* S = g_S + base;
    const int L = q + 1;
    const int tid = threadIdx.x;
    const float scale = 0.03125f;

    float pv[8];
    float m = -3.4e38f;
#pragma unroll
    for (int kk = 0; kk < 8; kk++) {
        int i = tid + kk * 256;
        pv[kk] = (i < L) ? S[i] : -3.4e38f;
        m = fmaxf(m, pv[kk]);
    }
#pragma unroll
    for (int off = 16; off; off >>= 1) m = fmaxf(m, __shfl_xor_sync(~0u, m, off));
    __shared__ float red[8];
    if ((tid & 31) == 0) red[tid >> 5] = m;
    __syncthreads();
    float mall = red[0];
#pragma unroll
    for (int j = 1; j < 8; j++) mall = fmaxf(mall, red[j]);
    __syncthreads();

    float sum = 0.f;
#pragma unroll
    for (int kk = 0; kk < 8; kk++) {
        int i = tid + kk * 256;
        if (i < L) { pv[kk] = expf((pv[kk] - mall) * scale); sum += pv[kk]; }
    }
#pragma unroll
    for (int off = 16; off; off >>= 1) sum += __shfl_xor_sync(~0u, sum, off);
    if ((tid & 31) == 0) red[tid >> 5] = sum;
    __syncthreads();
    float tot = 0.f;
#pragma unroll
    for (int j = 0; j < 8; j++) tot += red[j];
    const float inv = 1.0f / tot;

    const int Lpad = ((q >> 7) + 1) << 7;
#pragma unroll
    for (int kk = 0; kk < 8; kk++) {
        int i = tid + kk * 256;
        if (i < Lpad) {
            float p = (i < L) ? pv[kk] * inv : 0.f;
            bf16 h, l; split1(p, h, l);
            g_Ph[base + i] = h;
            g_Pl[base + i] = l;
        }
    }
}

// ---------------- GEMM 3: out = P @ V (heavy tiles first) ----------------
__global__ __launch_bounds__(256) void pv_mm(float* __restrict__ out)
{
    const int et = blockIdx.x, qt = (N_ / 128 - 1) - blockIdx.y, bt = blockIdx.z;
    extern __shared__ char smem[];
    float acc[2][8][4] = {};

    const size_t pb = (size_t)bt * N_ * N_ + (size_t)(qt * 128) * N_;
    const size_t vb = (size_t)bt * N_ * D_ + et * 128;
    mainloop<true>(g_Ph + pb, g_Pl + pb, N_,
                   g_Vh + vb, g_Vl + vb, D_,
                   (qt + 1) * 4, smem, acc);

    const int lane = threadIdx.x & 31, w = threadIdx.x >> 5;
    const int m0w = (w & 3) * 32, n0w = (w >> 2) * 64;
#pragma unroll
    for (int mt = 0; mt < 2; mt++)
#pragma unroll
        for (int nt = 0; nt < 8; nt++) {
            int q = qt * 128 + m0w + mt * 16 + (lane >> 2);
            int n = et * 128 + n0w + nt * 8 + (lane & 3) * 2;
            float* c = acc[mt][nt];
            float* O = out + ((size_t)bt * N_ + q) * D_ + n;
            *(float2*)O            = make_float2(c[0], c[1]);
            *(float2*)(O + 8 * D_) = make_float2(c[2], c[3]);
        }
}

// ---------------------------------------------------------------------------
extern "C" void kernel_launch(void* const* d_in, const int* in_sizes, int n_in,
                              void* d_out, int out_size)
{
    const float* x  = (const float*)d_in[0];
    const float* Wq = (const float*)d_in[1];
    const float* Wk = (const float*)d_in[2];
    const float* Wv = (const float*)d_in[3];
    float* out = (float*)d_out;

    cudaFuncSetAttribute(qkv_mm, cudaFuncAttributeMaxDynamicSharedMemorySize, SM_TOTAL);
    cudaFuncSetAttribute(qk_mm,  cudaFuncAttributeMaxDynamicSharedMemorySize, SM_TOTAL);
    cudaFuncSetAttribute(pv_mm,  cudaFuncAttributeMaxDynamicSharedMemorySize, SM_TOTAL);

    const int NT = N_ / 128;                       // 16
    const int NTRI = NT * (NT + 1) / 2;            // 136

    dim3 blk(256);
    convert_x<<<M_TOT * D_ / 4 / 256, blk>>>(x);
    convert_w<<<dim3(D_ * D_ / 4 / 256, 1, 3), blk>>>(Wq, Wk, Wv);
    qkv_mm<<<dim3(D_ / 128, M_TOT / 128, 3), blk, SM_TOTAL>>>();
    qk_mm<<<dim3(NTRI, 1, B_), blk, SM_TOTAL>>>();
    softmax_k<<<M_TOT, blk>>>();
    pv_mm<<<dim3(D_ / 128, NT, B_), blk, SM_TOTAL>>>(out);
}

// round 11
// speedup vs baseline: 1.1787x; 1.1787x over previous
#include <cuda_runtime.h>
#include <cuda_bf16.h>
#include <cstdint>

#define B_ 4
#define N_ 2048
#define D_ 1024
#define M_TOT (B_ * N_)

typedef __nv_bfloat16 bf16;

// ---------------- static device scratch ----------------
__device__ bf16  g_xh[M_TOT * D_],  g_xl[M_TOT * D_];
__device__ bf16  g_Wh[3 * D_ * D_], g_Wl[3 * D_ * D_];      // Wq, Wk, Wv [d][e] row-major
__device__ bf16  g_Mh[D_ * D_],     g_Ml[D_ * D_];          // M = Wq Wk^T  [d1][d2]
__device__ bf16  g_Qh[M_TOT * D_],  g_Ql[M_TOT * D_];       // Q' = x M
__device__ bf16  g_Vh[M_TOT * D_],  g_Vl[M_TOT * D_];       // V row-major
__device__ float g_S [(size_t)B_ * N_ * N_];
__device__ bf16  g_Ph[(size_t)B_ * N_ * N_], g_Pl[(size_t)B_ * N_ * N_];

// ---------------- smem: 3-stage ring, K-chunk = 32 (R6 proven config) ------
static constexpr int ARR = 8192;
static constexpr int STAGE = 4 * ARR;            // Ah, Al, Bh, Bl = 32768
static constexpr int NSTAGE = 3;
static constexpr int SM_TOTAL = NSTAGE * STAGE;  // 98304

__device__ __forceinline__ uint32_t swzN(uint32_t r, uint32_t c) {   // 64B rows
    return r * 64u + (c ^ ((r & 6u) << 3));
}
__device__ __forceinline__ uint32_t swzT(uint32_t r, uint32_t c) {   // 256B rows
    return r * 256u + (c ^ ((r & 7u) << 4));
}

// ---------------- PTX helpers ----------------
__device__ __forceinline__ uint32_t smem_u32(const void* p) {
    uint32_t a;
    asm("{ .reg .u64 t; cvta.to.shared.u64 t, %1; cvt.u32.u64 %0, t; }" : "=r"(a) : "l"(p));
    return a;
}
__device__ __forceinline__ void cp16(uint32_t dst, const void* src) {
    asm volatile("cp.async.cg.shared.global [%0], [%1], 16;" :: "r"(dst), "l"(src));
}
__device__ __forceinline__ void cp_commit() { asm volatile("cp.async.commit_group;"); }
__device__ __forceinline__ void cp_wait1()  { asm volatile("cp.async.wait_group 1;"); }

__device__ __forceinline__ void ldsm_x4(uint32_t r[4], uint32_t addr) {
    asm volatile("ldmatrix.sync.aligned.m8n8.x4.shared.b16 {%0,%1,%2,%3}, [%4];"
                 : "=r"(r[0]), "=r"(r[1]), "=r"(r[2]), "=r"(r[3]) : "r"(addr));
}
__device__ __forceinline__ void ldsm_x4_t(uint32_t r[4], uint32_t addr) {
    asm volatile("ldmatrix.sync.aligned.m8n8.x4.trans.shared.b16 {%0,%1,%2,%3}, [%4];"
                 : "=r"(r[0]), "=r"(r[1]), "=r"(r[2]), "=r"(r[3]) : "r"(addr));
}
__device__ __forceinline__ void mma16816(float c[4], const uint32_t a[4], uint32_t b0, uint32_t b1) {
    asm volatile("mma.sync.aligned.m16n8k16.row.col.f32.bf16.bf16.f32 "
                 "{%0,%1,%2,%3}, {%4,%5,%6,%7}, {%8,%9}, {%0,%1,%2,%3};"
                 : "+f"(c[0]), "+f"(c[1]), "+f"(c[2]), "+f"(c[3])
                 : "r"(a[0]), "r"(a[1]), "r"(a[2]), "r"(a[3]), "r"(b0), "r"(b1));
}

__device__ __forceinline__ unsigned pack2(bf16 a, bf16 b) {
    __nv_bfloat162 t(a, b);
    return *reinterpret_cast<unsigned*>(&t);
}
__device__ __forceinline__ void split1(float v, bf16& h, bf16& l) {
    h = __float2bfloat16(v);
    l = __float2bfloat16(v - __bfloat162float(h));
}

// ---------------------------------------------------------------------------
// acc(128x128) += A(128xK)*B^T, K chunks of 32, 3-stage cp.async ring (R6).
// ---------------------------------------------------------------------------
template <bool TRANSB>
__device__ __forceinline__ void mainloop(
    const bf16* __restrict__ Ah, const bf16* __restrict__ Al, int lda,
    const bf16* __restrict__ Bh, const bf16* __restrict__ Bl, int ldb,
    int nch, char* smem, float (&acc)[2][8][4])
{
    const uint32_t su = smem_u32(smem);
    const int tid = threadIdx.x;
    const int lane = tid & 31, w = tid >> 5;
    const int m0w = (w & 3) * 32, n0w = (w >> 2) * 64;

    const int arow = tid >> 1;
    const int ac0  = (tid & 1) * 32;
    const int tkr = tid >> 4, tseg = tid & 15;

    auto load_chunk = [&](int ch, int st) {
        const int k0 = ch * 32;
        const uint32_t base = su + st * STAGE;
        const bf16* pAh = Ah + (size_t)arow * lda + k0 + (ac0 >> 1);
        const bf16* pAl = Al + (size_t)arow * lda + k0 + (ac0 >> 1);
        uint32_t d0 = base + swzN(arow, ac0);
        uint32_t d1 = base + swzN(arow, ac0 + 16);
        cp16(d0, pAh);            cp16(d1, pAh + 8);
        cp16(d0 + ARR, pAl);      cp16(d1 + ARR, pAl + 8);
        if (!TRANSB) {
            const bf16* pBh = Bh + (size_t)arow * ldb + k0 + (ac0 >> 1);
            const bf16* pBl = Bl + (size_t)arow * ldb + k0 + (ac0 >> 1);
            uint32_t e0 = base + 2 * ARR + swzN(arow, ac0);
            uint32_t e1 = base + 2 * ARR + swzN(arow, ac0 + 16);
            cp16(e0, pBh);        cp16(e1, pBh + 8);
            cp16(e0 + ARR, pBl);  cp16(e1 + ARR, pBl + 8);
        } else {
            const bf16* pBh0 = Bh + (size_t)(k0 + tkr) * ldb + tseg * 8;
            const bf16* pBl0 = Bl + (size_t)(k0 + tkr) * ldb + tseg * 8;
            const bf16* pBh1 = Bh + (size_t)(k0 + tkr + 16) * ldb + tseg * 8;
            const bf16* pBl1 = Bl + (size_t)(k0 + tkr + 16) * ldb + tseg * 8;
            uint32_t e0 = base + 2 * ARR + swzT(tkr, tseg * 16);
            uint32_t e1 = base + 2 * ARR + swzT(tkr + 16, tseg * 16);
            cp16(e0, pBh0);       cp16(e0 + ARR, pBl0);
            cp16(e1, pBh1);       cp16(e1 + ARR, pBl1);
        }
    };

    load_chunk(0, 0); cp_commit();
    if (nch > 1) load_chunk(1, 1);
    cp_commit();

    for (int ch = 0; ch < nch; ch++) {
        cp_wait1();
        __syncthreads();
        if (ch + 2 < nch) load_chunk(ch + 2, (ch + 2) % 3);
        cp_commit();

        const uint32_t base = su + (ch % 3) * STAGE;
#pragma unroll
        for (int kk = 0; kk < 2; kk++) {
            uint32_t Af[2][4], Alf[2][4];
            {
                const uint32_t r0 = m0w + (lane & 15);
                const uint32_t c0 = (lane >> 4) * 16 + kk * 32;
#pragma unroll
                for (int mt = 0; mt < 2; mt++) {
                    uint32_t a0 = base + swzN(r0 + mt * 16, c0);
                    ldsm_x4(Af[mt],  a0);
                    ldsm_x4(Alf[mt], a0 + ARR);
                }
            }
#pragma unroll
            for (int p = 0; p < 4; p++) {
                uint32_t q[4], ql[4];
                if (!TRANSB) {
                    const uint32_t r0 = n0w + (lane & 7) + ((lane >> 4) << 3) + p * 16;
                    const uint32_t c0 = ((lane >> 3) & 1) * 16 + kk * 32;
                    uint32_t b0 = base + 2 * ARR + swzN(r0, c0);
                    ldsm_x4(q,  b0);
                    ldsm_x4(ql, b0 + ARR);
                } else {
                    const uint32_t r0 = (lane & 15) + kk * 16;
                    const uint32_t c0 = (lane >> 4) * 16 + n0w * 2 + p * 32;
                    uint32_t b0 = base + 2 * ARR + swzT(r0, c0);
                    ldsm_x4_t(q,  b0);
                    ldsm_x4_t(ql, b0 + ARR);
                }
                const int nt0 = 2 * p, nt1 = 2 * p + 1;
                mma16816(acc[0][nt0], Af[0],  q[0],  q[1]);
                mma16816(acc[1][nt0], Af[1],  q[0],  q[1]);
                mma16816(acc[0][nt1], Af[0],  q[2],  q[3]);
                mma16816(acc[1][nt1], Af[1],  q[2],  q[3]);

                mma16816(acc[0][nt0], Af[0],  ql[0], ql[1]);
                mma16816(acc[1][nt0], Af[1],  ql[0], ql[1]);
                mma16816(acc[0][nt1], Af[0],  ql[2], ql[3]);
                mma16816(acc[1][nt1], Af[1],  ql[2], ql[3]);

                mma16816(acc[0][nt0], Alf[0], q[0],  q[1]);
                mma16816(acc[1][nt0], Alf[1], q[0],  q[1]);
                mma16816(acc[0][nt1], Alf[0], q[2],  q[3]);
                mma16816(acc[1][nt1], Alf[1], q[2],  q[3]);
            }
        }
    }
    __syncthreads();
}

// ---------------- precompute: fp32 -> bf16 hi/lo splits ----------------
__global__ __launch_bounds__(256) void convert_x(const float* __restrict__ x)
{
    size_t idx = (size_t)(blockIdx.x * 256 + threadIdx.x) * 4;
    float4 v = *(const float4*)(x + idx);
    bf16 h[4], l[4];
    split1(v.x, h[0], l[0]); split1(v.y, h[1], l[1]);
    split1(v.z, h[2], l[2]); split1(v.w, h[3], l[3]);
    *(uint2*)(g_xh + idx) = make_uint2(pack2(h[0], h[1]), pack2(h[2], h[3]));
    *(uint2*)(g_xl + idx) = make_uint2(pack2(l[0], l[1]), pack2(l[2], l[3]));
}

__global__ __launch_bounds__(256) void convert_w(
    const float* __restrict__ Wq, const float* __restrict__ Wk, const float* __restrict__ Wv)
{
    const float* W = (blockIdx.z == 0) ? Wq : (blockIdx.z == 1) ? Wk : Wv;
    size_t base = (size_t)blockIdx.z * D_ * D_;
    size_t idx = (size_t)(blockIdx.x * 256 + threadIdx.x) * 4;
    float4 v = *(const float4*)(W + idx);
    bf16 h[4], l[4];
    split1(v.x, h[0], l[0]); split1(v.y, h[1], l[1]);
    split1(v.z, h[2], l[2]); split1(v.w, h[3], l[3]);
    *(uint2*)(g_Wh + base + idx) = make_uint2(pack2(h[0], h[1]), pack2(h[2], h[3]));
    *(uint2*)(g_Wl + base + idx) = make_uint2(pack2(l[0], l[1]), pack2(l[2], l[3]));
}

// ---------------- GEMM 0: M = Wq @ Wk^T  (1024x1024, tiny) ----------------
__global__ __launch_bounds__(256, 2) void wqk_mm()
{
    extern __shared__ char smem[];
    const int n0 = blockIdx.x * 128, m0 = blockIdx.y * 128;
    float acc[2][8][4] = {};

    // A = Wq rows [d1][e]; B = Wk rows [d2][e] (n-rows, k contiguous) -> TRANSB=false
    mainloop<false>(g_Wh + (size_t)m0 * D_, g_Wl + (size_t)m0 * D_, D_,
                    g_Wh + (size_t)D_ * D_ + (size_t)n0 * D_,
                    g_Wl + (size_t)D_ * D_ + (size_t)n0 * D_, D_,
                    D_ / 32, smem, acc);

    const int lane = threadIdx.x & 31, w = threadIdx.x >> 5;
    const int m0w = (w & 3) * 32, n0w = (w >> 2) * 64;
#pragma unroll
    for (int mt = 0; mt < 2; mt++)
#pragma unroll
        for (int nt = 0; nt < 8; nt++) {
            int m = m0 + m0w + mt * 16 + (lane >> 2);
            int n = n0 + n0w + nt * 8 + (lane & 3) * 2;
            float* c = acc[mt][nt];
            bf16 h0, l0, h1, l1;
            split1(c[0], h0, l0); split1(c[1], h1, l1);
            *(unsigned*)(g_Mh + (size_t)m * D_ + n) = pack2(h0, h1);
            *(unsigned*)(g_Ml + (size_t)m * D_ + n) = pack2(l0, l1);
            split1(c[2], h0, l0); split1(c[3], h1, l1);
            *(unsigned*)(g_Mh + (size_t)(m + 8) * D_ + n) = pack2(h0, h1);
            *(unsigned*)(g_Ml + (size_t)(m + 8) * D_ + n) = pack2(l0, l1);
        }
}

// ---------------- GEMM 1: Q' = x @ M,  V = x @ Wv ----------------
__global__ __launch_bounds__(256, 2) void qv_mm()
{
    extern __shared__ char smem[];
    const int n0 = blockIdx.x * 128, m0 = blockIdx.y * 128, z = blockIdx.z;
    float acc[2][8][4] = {};

    const bf16* Bh = (z == 0) ? g_Mh : (g_Wh + (size_t)2 * D_ * D_);
    const bf16* Bl = (z == 0) ? g_Ml : (g_Wl + (size_t)2 * D_ * D_);
    mainloop<true>(g_xh + (size_t)m0 * D_, g_xl + (size_t)m0 * D_, D_,
                   Bh + n0, Bl + n0, D_,
                   D_ / 32, smem, acc);

    bf16* Oh = (z == 0) ? g_Qh : g_Vh;
    bf16* Ol = (z == 0) ? g_Ql : g_Vl;
    const int lane = threadIdx.x & 31, w = threadIdx.x >> 5;
    const int m0w = (w & 3) * 32, n0w = (w >> 2) * 64;
#pragma unroll
    for (int mt = 0; mt < 2; mt++)
#pragma unroll
        for (int nt = 0; nt < 8; nt++) {
            int m = m0 + m0w + mt * 16 + (lane >> 2);
            int n = n0 + n0w + nt * 8 + (lane & 3) * 2;
            float* c = acc[mt][nt];
            bf16 h0, l0, h1, l1;
            split1(c[0], h0, l0); split1(c[1], h1, l1);
            *(unsigned*)(Oh + (size_t)m * D_ + n) = pack2(h0, h1);
            *(unsigned*)(Ol + (size_t)m * D_ + n) = pack2(l0, l1);
            split1(c[2], h0, l0); split1(c[3], h1, l1);
            *(unsigned*)(Oh + (size_t)(m + 8) * D_ + n) = pack2(h0, h1);
            *(unsigned*)(Ol + (size_t)(m + 8) * D_ + n) = pack2(l0, l1);
        }
}

// ---------------- GEMM 2: S = Q' @ x^T (compact triangular grid) ----------
__global__ __launch_bounds__(256, 2) void qk_mm()
{
    const int i = blockIdx.x, bt = blockIdx.z;
    int qt = (int)((sqrtf(8.0f * i + 1.0f) - 1.0f) * 0.5f);
    while ((qt + 1) * (qt + 2) / 2 <= i) qt++;
    while (qt * (qt + 1) / 2 > i) qt--;
    const int kt = i - qt * (qt + 1) / 2;

    extern __shared__ char smem[];
    float acc[2][8][4] = {};

    const size_t rb = (size_t)bt * N_ * D_;
    mainloop<false>(g_Qh + rb + (size_t)qt * 128 * D_, g_Ql + rb + (size_t)qt * 128 * D_, D_,
                    g_xh + rb + (size_t)kt * 128 * D_, g_xl + rb + (size_t)kt * 128 * D_, D_,
                    D_ / 32, smem, acc);

    float* S = g_S + (size_t)bt * N_ * N_;
    const int lane = threadIdx.x & 31, w = threadIdx.x >> 5;
    const int m0w = (w & 3) * 32, n0w = (w >> 2) * 64;
#pragma unroll
    for (int mt = 0; mt < 2; mt++)
#pragma unroll
        for (int nt = 0; nt < 8; nt++) {
            int q = qt * 128 + m0w + mt * 16 + (lane >> 2);
            int n = kt * 128 + n0w + nt * 8 + (lane & 3) * 2;
            float* c = acc[mt][nt];
            *(float2*)(S + (size_t)q * N_ + n)       = make_float2(c[0], c[1]);
            *(float2*)(S + (size_t)(q + 8) * N_ + n) = make_float2(c[2], c[3]);
        }
}

// ---------------- softmax -> P bf16 hi/lo (zero-padded to tile) ----------
__global__ __launch_bounds__(256) void softmax_k()
{
    const int row = blockIdx.x;
    const int bt = row >> 11;
    const int q  = row & (N_ - 1);
    const size_t base = (size_t)bt * N_ * N_ + (size_t)q * N_;
    const float* S = g_S + base;
    const int L = q + 1;
    const int tid = threadIdx.x;
    const float scale = 0.03125f;

    float pv[8];
    float m = -3.4e38f;
#pragma unroll
    for (int kk = 0; kk < 8; kk++) {
        int i = tid + kk * 256;
        pv[kk] = (i < L) ? S[i] : -3.4e38f;
        m = fmaxf(m, pv[kk]);
    }
#pragma unroll
    for (int off = 16; off; off >>= 1) m = fmaxf(m, __shfl_xor_sync(~0u, m, off));
    __shared__ float red[8];
    if ((tid & 31) == 0) red[tid >> 5] = m;
    __syncthreads();
    float mall = red[0];
#pragma unroll
    for (int j = 1; j < 8; j++) mall = fmaxf(mall, red[j]);
    __syncthreads();

    float sum = 0.f;
#pragma unroll
    for (int kk = 0; kk < 8; kk++) {
        int i = tid + kk * 256;
        if (i < L) { pv[kk] = expf((pv[kk] - mall) * scale); sum += pv[kk]; }
    }
#pragma unroll
    for (int off = 16; off; off >>= 1) sum += __shfl_xor_sync(~0u, sum, off);
    if ((tid & 31) == 0) red[tid >> 5] = sum;
    __syncthreads();
    float tot = 0.f;
#pragma unroll
    for (int j = 0; j < 8; j++) tot += red[j];
    const float inv = 1.0f / tot;

    const int Lpad = ((q >> 7) + 1) << 7;
#pragma unroll
    for (int kk = 0; kk < 8; kk++) {
        int i = tid + kk * 256;
        if (i < Lpad) {
            float p = (i < L) ? pv[kk] * inv : 0.f;
            bf16 h, l; split1(p, h, l);
            g_Ph[base + i] = h;
            g_Pl[base + i] = l;
        }
    }
}

// ---------------- GEMM 3: out = P @ V (heavy tiles first) ----------------
__global__ __launch_bounds__(256, 2) void pv_mm(float* __restrict__ out)
{
    const int et = blockIdx.x, qt = (N_ / 128 - 1) - blockIdx.y, bt = blockIdx.z;
    extern __shared__ char smem[];
    float acc[2][8][4] = {};

    const size_t pb = (size_t)bt * N_ * N_ + (size_t)(qt * 128) * N_;
    const size_t vb = (size_t)bt * N_ * D_ + et * 128;
    mainloop<true>(g_Ph + pb, g_Pl + pb, N_,
                   g_Vh + vb, g_Vl + vb, D_,
                   (qt + 1) * 4, smem, acc);

    const int lane = threadIdx.x & 31, w = threadIdx.x >> 5;
    const int m0w = (w & 3) * 32, n0w = (w >> 2) * 64;
#pragma unroll
    for (int mt = 0; mt < 2; mt++)
#pragma unroll
        for (int nt = 0; nt < 8; nt++) {
            int q = qt * 128 + m0w + mt * 16 + (lane >> 2);
            int n = et * 128 + n0w + nt * 8 + (lane & 3) * 2;
            float* c = acc[mt][nt];
            float* O = out + ((size_t)bt * N_ + q) * D_ + n;
            *(float2*)O            = make_float2(c[0], c[1]);
            *(float2*)(O + 8 * D_) = make_float2(c[2], c[3]);
        }
}

// ---------------------------------------------------------------------------
extern "C" void kernel_launch(void* const* d_in, const int* in_sizes, int n_in,
                              void* d_out, int out_size)
{
    const float* x  = (const float*)d_in[0];
    const float* Wq = (const float*)d_in[1];
    const float* Wk = (const float*)d_in[2];
    const float* Wv = (const float*)d_in[3];
    float* out = (float*)d_out;

    cudaFuncSetAttribute(wqk_mm, cudaFuncAttributeMaxDynamicSharedMemorySize, SM_TOTAL);
    cudaFuncSetAttribute(qv_mm,  cudaFuncAttributeMaxDynamicSharedMemorySize, SM_TOTAL);
    cudaFuncSetAttribute(qk_mm,  cudaFuncAttributeMaxDynamicSharedMemorySize, SM_TOTAL);
    cudaFuncSetAttribute(pv_mm,  cudaFuncAttributeMaxDynamicSharedMemorySize, SM_TOTAL);

    const int NT = N_ / 128;                       // 16
    const int NTRI = NT * (NT + 1) / 2;            // 136

    dim3 blk(256);
    convert_x<<<M_TOT * D_ / 4 / 256, blk>>>(x);
    convert_w<<<dim3(D_ * D_ / 4 / 256, 1, 3), blk>>>(Wq, Wk, Wv);
    wqk_mm<<<dim3(D_ / 128, D_ / 128, 1), blk, SM_TOTAL>>>();
    qv_mm<<<dim3(D_ / 128, M_TOT / 128, 2), blk, SM_TOTAL>>>();
    qk_mm<<<dim3(NTRI, 1, B_), blk, SM_TOTAL>>>();
    softmax_k<<<M_TOT, blk>>>();
    pv_mm<<<dim3(D_ / 128, NT, B_), blk, SM_TOTAL>>>(out);
}

// round 16
// speedup vs baseline: 1.4001x; 1.1878x over previous
#include <cuda_runtime.h>
#include <cuda_bf16.h>
#include <cuda_fp16.h>
#include <cstdint>

#define B_ 4
#define N_ 2048
#define D_ 1024
#define M_TOT (B_ * N_)

typedef __nv_bfloat16 bf16;

// ---------------- static device scratch ----------------
__device__ __align__(16) bf16  g_xh[M_TOT * D_],  g_xl[M_TOT * D_];
__device__ __align__(16) bf16  g_Wh[3 * D_ * D_], g_Wl[3 * D_ * D_];
__device__ __align__(16) bf16  g_Mh[D_ * D_],     g_Ml[D_ * D_];
__device__ __align__(16) bf16  g_Qh[M_TOT * D_],  g_Ql[M_TOT * D_];
__device__ __align__(16) __half g_V16[M_TOT * D_];              // V single fp16
__device__ __align__(16) float g_S [(size_t)B_ * N_ * N_];
__device__ __align__(16) __half g_P16[(size_t)B_ * N_ * N_];    // P single fp16

// ---------------- bf16 smem: 3-stage ring, K-chunk = 32 ----------------
static constexpr int ARR = 8192;
static constexpr int STAGE = 4 * ARR;
static constexpr int NSTAGE = 3;
static constexpr int SM_TOTAL = NSTAGE * STAGE;   // 98304

// ---------------- fp16 single-limb smem (PV): 3-stage ----------------
static constexpr int STAGE1 = 2 * ARR;            // A, B only = 16384
static constexpr int SM_PV = NSTAGE * STAGE1;     // 49152

__device__ __forceinline__ uint32_t swzN(uint32_t r, uint32_t c) {
    return r * 64u + (c ^ ((r & 6u) << 3));
}
__device__ __forceinline__ uint32_t swzT(uint32_t r, uint32_t c) {
    return r * 256u + (c ^ ((r & 7u) << 4));
}

// ---------------- PTX helpers ----------------
__device__ __forceinline__ uint32_t smem_u32(const void* p) {
    uint32_t a;
    asm("{ .reg .u64 t; cvta.to.shared.u64 t, %1; cvt.u32.u64 %0, t; }" : "=r"(a) : "l"(p));
    return a;
}
__device__ __forceinline__ void cp16(uint32_t dst, const void* src) {
    asm volatile("cp.async.cg.shared.global [%0], [%1], 16;" :: "r"(dst), "l"(src));
}
__device__ __forceinline__ void cp_commit() { asm volatile("cp.async.commit_group;"); }
__device__ __forceinline__ void cp_wait1()  { asm volatile("cp.async.wait_group 1;"); }

__device__ __forceinline__ void ldsm_x4(uint32_t r[4], uint32_t addr) {
    asm volatile("ldmatrix.sync.aligned.m8n8.x4.shared.b16 {%0,%1,%2,%3}, [%4];"
                 : "=r"(r[0]), "=r"(r[1]), "=r"(r[2]), "=r"(r[3]) : "r"(addr));
}
__device__ __forceinline__ void ldsm_x4_t(uint32_t r[4], uint32_t addr) {
    asm volatile("ldmatrix.sync.aligned.m8n8.x4.trans.shared.b16 {%0,%1,%2,%3}, [%4];"
                 : "=r"(r[0]), "=r"(r[1]), "=r"(r[2]), "=r"(r[3]) : "r"(addr));
}
__device__ __forceinline__ void mma16816(float c[4], const uint32_t a[4], uint32_t b0, uint32_t b1) {
    asm volatile("mma.sync.aligned.m16n8k16.row.col.f32.bf16.bf16.f32 "
                 "{%0,%1,%2,%3}, {%4,%5,%6,%7}, {%8,%9}, {%0,%1,%2,%3};"
                 : "+f"(c[0]), "+f"(c[1]), "+f"(c[2]), "+f"(c[3])
                 : "r"(a[0]), "r"(a[1]), "r"(a[2]), "r"(a[3]), "r"(b0), "r"(b1));
}
__device__ __forceinline__ void mma16816h(float c[4], const uint32_t a[4], uint32_t b0, uint32_t b1) {
    asm volatile("mma.sync.aligned.m16n8k16.row.col.f32.f16.f16.f32 "
                 "{%0,%1,%2,%3}, {%4,%5,%6,%7}, {%8,%9}, {%0,%1,%2,%3};"
                 : "+f"(c[0]), "+f"(c[1]), "+f"(c[2]), "+f"(c[3])
                 : "r"(a[0]), "r"(a[1]), "r"(a[2]), "r"(a[3]), "r"(b0), "r"(b1));
}

__device__ __forceinline__ unsigned pack2(bf16 a, bf16 b) {
    __nv_bfloat162 t(a, b);
    return *reinterpret_cast<unsigned*>(&t);
}
__device__ __forceinline__ void split1(float v, bf16& h, bf16& l) {
    h = __float2bfloat16(v);
    l = __float2bfloat16(v - __bfloat162float(h));
}

// ---------------------------------------------------------------------------
// bf16 split mainloop (R11 proven): acc += A(128xK)*B^T, chunks of 32.
// ---------------------------------------------------------------------------
template <bool TRANSB>
__device__ __forceinline__ void mainloop(
    const bf16* __restrict__ Ah, const bf16* __restrict__ Al, int lda,
    const bf16* __restrict__ Bh, const bf16* __restrict__ Bl, int ldb,
    int nch, char* smem, float (&acc)[2][8][4])
{
    const uint32_t su = smem_u32(smem);
    const int tid = threadIdx.x;
    const int lane = tid & 31, w = tid >> 5;
    const int m0w = (w & 3) * 32, n0w = (w >> 2) * 64;

    const int arow = tid >> 1;
    const int ac0  = (tid & 1) * 32;
    const int tkr = tid >> 4, tseg = tid & 15;

    auto load_chunk = [&](int ch, int st) {
        const int k0 = ch * 32;
        const uint32_t base = su + st * STAGE;
        const bf16* pAh = Ah + (size_t)arow * lda + k0 + (ac0 >> 1);
        const bf16* pAl = Al + (size_t)arow * lda + k0 + (ac0 >> 1);
        uint32_t d0 = base + swzN(arow, ac0);
        uint32_t d1 = base + swzN(arow, ac0 + 16);
        cp16(d0, pAh);            cp16(d1, pAh + 8);
        cp16(d0 + ARR, pAl);      cp16(d1 + ARR, pAl + 8);
        if (!TRANSB) {
            const bf16* pBh = Bh + (size_t)arow * ldb + k0 + (ac0 >> 1);
            const bf16* pBl = Bl + (size_t)arow * ldb + k0 + (ac0 >> 1);
            uint32_t e0 = base + 2 * ARR + swzN(arow, ac0);
            uint32_t e1 = base + 2 * ARR + swzN(arow, ac0 + 16);
            cp16(e0, pBh);        cp16(e1, pBh + 8);
            cp16(e0 + ARR, pBl);  cp16(e1 + ARR, pBl + 8);
        } else {
            const bf16* pBh0 = Bh + (size_t)(k0 + tkr) * ldb + tseg * 8;
            const bf16* pBl0 = Bl + (size_t)(k0 + tkr) * ldb + tseg * 8;
            const bf16* pBh1 = Bh + (size_t)(k0 + tkr + 16) * ldb + tseg * 8;
            const bf16* pBl1 = Bl + (size_t)(k0 + tkr + 16) * ldb + tseg * 8;
            uint32_t e0 = base + 2 * ARR + swzT(tkr, tseg * 16);
            uint32_t e1 = base + 2 * ARR + swzT(tkr + 16, tseg * 16);
            cp16(e0, pBh0);       cp16(e0 + ARR, pBl0);
            cp16(e1, pBh1);       cp16(e1 + ARR, pBl1);
        }
    };

    load_chunk(0, 0); cp_commit();
    if (nch > 1) load_chunk(1, 1);
    cp_commit();

    for (int ch = 0; ch < nch; ch++) {
        cp_wait1();
        __syncthreads();
        if (ch + 2 < nch) load_chunk(ch + 2, (ch + 2) % 3);
        cp_commit();

        const uint32_t base = su + (ch % 3) * STAGE;
#pragma unroll
        for (int kk = 0; kk < 2; kk++) {
            uint32_t Af[2][4], Alf[2][4];
            {
                const uint32_t r0 = m0w + (lane & 15);
                const uint32_t c0 = (lane >> 4) * 16 + kk * 32;
#pragma unroll
                for (int mt = 0; mt < 2; mt++) {
                    uint32_t a0 = base + swzN(r0 + mt * 16, c0);
                    ldsm_x4(Af[mt],  a0);
                    ldsm_x4(Alf[mt], a0 + ARR);
                }
            }
#pragma unroll
            for (int p = 0; p < 4; p++) {
                uint32_t q[4], ql[4];
                if (!TRANSB) {
                    const uint32_t r0 = n0w + (lane & 7) + ((lane >> 4) << 3) + p * 16;
                    const uint32_t c0 = ((lane >> 3) & 1) * 16 + kk * 32;
                    uint32_t b0 = base + 2 * ARR + swzN(r0, c0);
                    ldsm_x4(q,  b0);
                    ldsm_x4(ql, b0 + ARR);
                } else {
                    const uint32_t r0 = (lane & 15) + kk * 16;
                    const uint32_t c0 = (lane >> 4) * 16 + n0w * 2 + p * 32;
                    uint32_t b0 = base + 2 * ARR + swzT(r0, c0);
                    ldsm_x4_t(q,  b0);
                    ldsm_x4_t(ql, b0 + ARR);
                }
                const int nt0 = 2 * p, nt1 = 2 * p + 1;
                mma16816(acc[0][nt0], Af[0],  q[0],  q[1]);
                mma16816(acc[1][nt0], Af[1],  q[0],  q[1]);
                mma16816(acc[0][nt1], Af[0],  q[2],  q[3]);
                mma16816(acc[1][nt1], Af[1],  q[2],  q[3]);

                mma16816(acc[0][nt0], Af[0],  ql[0], ql[1]);
                mma16816(acc[1][nt0], Af[1],  ql[0], ql[1]);
                mma16816(acc[0][nt1], Af[0],  ql[2], ql[3]);
                mma16816(acc[1][nt1], Af[1],  ql[2], ql[3]);

                mma16816(acc[0][nt0], Alf[0], q[0],  q[1]);
                mma16816(acc[1][nt0], Alf[1], q[0],  q[1]);
                mma16816(acc[0][nt1], Alf[0], q[2],  q[3]);
                mma16816(acc[1][nt1], Alf[1], q[2],  q[3]);
            }
        }
    }
    __syncthreads();
}

// ---------------------------------------------------------------------------
// fp16 single-limb mainloop (PV): acc += A(128xK)*B^T, A rows [m][k],
// B rows [k][n] (trans). 1 MMA per fragment pair.
// ---------------------------------------------------------------------------
__device__ __forceinline__ void mainloop_h1(
    const __half* __restrict__ A, int lda,
    const __half* __restrict__ Bt, int ldb,
    int nch, char* smem, float (&acc)[2][8][4])
{
    const uint32_t su = smem_u32(smem);
    const int tid = threadIdx.x;
    const int lane = tid & 31, w = tid >> 5;
    const int m0w = (w & 3) * 32, n0w = (w >> 2) * 64;

    const int arow = tid >> 1;
    const int ac0  = (tid & 1) * 32;
    const int tkr = tid >> 4, tseg = tid & 15;

    auto load_chunk = [&](int ch, int st) {
        const int k0 = ch * 32;
        const uint32_t base = su + st * STAGE1;
        const __half* pA = A + (size_t)arow * lda + k0 + (ac0 >> 1);
        cp16(base + swzN(arow, ac0),      pA);
        cp16(base + swzN(arow, ac0 + 16), pA + 8);
        const __half* pB0 = Bt + (size_t)(k0 + tkr) * ldb + tseg * 8;
        const __half* pB1 = Bt + (size_t)(k0 + tkr + 16) * ldb + tseg * 8;
        cp16(base + ARR + swzT(tkr, tseg * 16),      pB0);
        cp16(base + ARR + swzT(tkr + 16, tseg * 16), pB1);
    };

    load_chunk(0, 0); cp_commit();
    if (nch > 1) load_chunk(1, 1);
    cp_commit();

    for (int ch = 0; ch < nch; ch++) {
        cp_wait1();
        __syncthreads();
        if (ch + 2 < nch) load_chunk(ch + 2, (ch + 2) % 3);
        cp_commit();

        const uint32_t base = su + (ch % 3) * STAGE1;
#pragma unroll
        for (int kk = 0; kk < 2; kk++) {
            uint32_t Af[2][4];
            {
                const uint32_t r0 = m0w + (lane & 15);
                const uint32_t c0 = (lane >> 4) * 16 + kk * 32;
#pragma unroll
                for (int mt = 0; mt < 2; mt++)
                    ldsm_x4(Af[mt], base + swzN(r0 + mt * 16, c0));
            }
#pragma unroll
            for (int p = 0; p < 4; p++) {
                uint32_t q[4];
                const uint32_t r0 = (lane & 15) + kk * 16;
                const uint32_t c0 = (lane >> 4) * 16 + n0w * 2 + p * 32;
                ldsm_x4_t(q, base + ARR + swzT(r0, c0));
                const int nt0 = 2 * p, nt1 = 2 * p + 1;
                mma16816h(acc[0][nt0], Af[0], q[0], q[1]);
                mma16816h(acc[1][nt0], Af[1], q[0], q[1]);
                mma16816h(acc[0][nt1], Af[0], q[2], q[3]);
                mma16816h(acc[1][nt1], Af[1], q[2], q[3]);
            }
        }
    }
    __syncthreads();
}

// ---------------- precompute: fp32 -> bf16 hi/lo splits ----------------
__global__ __launch_bounds__(256) void convert_x(const float* __restrict__ x)
{
    size_t idx = (size_t)(blockIdx.x * 256 + threadIdx.x) * 4;
    float4 v = *(const float4*)(x + idx);
    bf16 h[4], l[4];
    split1(v.x, h[0], l[0]); split1(v.y, h[1], l[1]);
    split1(v.z, h[2], l[2]); split1(v.w, h[3], l[3]);
    *(uint2*)(g_xh + idx) = make_uint2(pack2(h[0], h[1]), pack2(h[2], h[3]));
    *(uint2*)(g_xl + idx) = make_uint2(pack2(l[0], l[1]), pack2(l[2], l[3]));
}

__global__ __launch_bounds__(256) void convert_w(
    const float* __restrict__ Wq, const float* __restrict__ Wk, const float* __restrict__ Wv)
{
    const float* W = (blockIdx.z == 0) ? Wq : (blockIdx.z == 1) ? Wk : Wv;
    size_t base = (size_t)blockIdx.z * D_ * D_;
    size_t idx = (size_t)(blockIdx.x * 256 + threadIdx.x) * 4;
    float4 v = *(const float4*)(W + idx);
    bf16 h[4], l[4];
    split1(v.x, h[0], l[0]); split1(v.y, h[1], l[1]);
    split1(v.z, h[2], l[2]); split1(v.w, h[3], l[3]);
    *(uint2*)(g_Wh + base + idx) = make_uint2(pack2(h[0], h[1]), pack2(h[2], h[3]));
    *(uint2*)(g_Wl + base + idx) = make_uint2(pack2(l[0], l[1]), pack2(l[2], l[3]));
}

// ---------------- GEMM 0: M = Wq @ Wk^T (bf16 split) ----------------
__global__ __launch_bounds__(256, 2) void wqk_mm()
{
    extern __shared__ char smem[];
    const int n0 = blockIdx.x * 128, m0 = blockIdx.y * 128;
    float acc[2][8][4] = {};

    mainloop<false>(g_Wh + (size_t)m0 * D_, g_Wl + (size_t)m0 * D_, D_,
                    g_Wh + (size_t)D_ * D_ + (size_t)n0 * D_,
                    g_Wl + (size_t)D_ * D_ + (size_t)n0 * D_, D_,
                    D_ / 32, smem, acc);

    const int lane = threadIdx.x & 31, w = threadIdx.x >> 5;
    const int m0w = (w & 3) * 32, n0w = (w >> 2) * 64;
#pragma unroll
    for (int mt = 0; mt < 2; mt++)
#pragma unroll
        for (int nt = 0; nt < 8; nt++) {
            int m = m0 + m0w + mt * 16 + (lane >> 2);
            int n = n0 + n0w + nt * 8 + (lane & 3) * 2;
            float* c = acc[mt][nt];
            bf16 h0, l0, h1, l1;
            split1(c[0], h0, l0); split1(c[1], h1, l1);
            *(unsigned*)(g_Mh + (size_t)n * D_ + m - (n - n) ) , (void)0;
            // store M^T-style? No: M[m][n] with A=Wq rows (d1) x B=Wk rows (d2):
            // we need M[d1][d2]; m indexes d1, n indexes d2 -> row-major at [m][n].
            *(unsigned*)(g_Mh + (size_t)m * D_ + n) = pack2(h0, h1);
            *(unsigned*)(g_Ml + (size_t)m * D_ + n) = pack2(l0, l1);
            split1(c[2], h0, l0); split1(c[3], h1, l1);
            *(unsigned*)(g_Mh + (size_t)(m + 8) * D_ + n) = pack2(h0, h1);
            *(unsigned*)(g_Ml + (size_t)(m + 8) * D_ + n) = pack2(l0, l1);
        }
}

// ---------------- GEMM 1: Q' = x @ M^T rows? ------------------------------
// Q'[t][d2] = sum_d1 x[t][d1] M[d1][d2]; with M rows [d1][d2] -> TRANSB=true.
// V = x @ Wv (TRANSB=true), epilogue -> single fp16.
__global__ __launch_bounds__(256, 2) void qv_mm()
{
    extern __shared__ char smem[];
    const int n0 = blockIdx.x * 128, m0 = blockIdx.y * 128, z = blockIdx.z;
    float acc[2][8][4] = {};

    const bf16* Bh = (z == 0) ? g_Mh : (g_Wh + (size_t)2 * D_ * D_);
    const bf16* Bl = (z == 0) ? g_Ml : (g_Wl + (size_t)2 * D_ * D_);
    mainloop<true>(g_xh + (size_t)m0 * D_, g_xl + (size_t)m0 * D_, D_,
                   Bh + n0, Bl + n0, D_,
                   D_ / 32, smem, acc);

    const int lane = threadIdx.x & 31, w = threadIdx.x >> 5;
    const int m0w = (w & 3) * 32, n0w = (w >> 2) * 64;
#pragma unroll
    for (int mt = 0; mt < 2; mt++)
#pragma unroll
        for (int nt = 0; nt < 8; nt++) {
            int m = m0 + m0w + mt * 16 + (lane >> 2);
            int n = n0 + n0w + nt * 8 + (lane & 3) * 2;
            float* c = acc[mt][nt];
            if (z == 0) {
                bf16 h0, l0, h1, l1;
                split1(c[0], h0, l0); split1(c[1], h1, l1);
                *(unsigned*)(g_Qh + (size_t)m * D_ + n) = pack2(h0, h1);
                *(unsigned*)(g_Ql + (size_t)m * D_ + n) = pack2(l0, l1);
                split1(c[2], h0, l0); split1(c[3], h1, l1);
                *(unsigned*)(g_Qh + (size_t)(m + 8) * D_ + n) = pack2(h0, h1);
                *(unsigned*)(g_Ql + (size_t)(m + 8) * D_ + n) = pack2(l0, l1);
            } else {
                __half2 v01 = __floats2half2_rn(c[0], c[1]);
                __half2 v23 = __floats2half2_rn(c[2], c[3]);
                *(__half2*)(g_V16 + (size_t)m * D_ + n)       = v01;
                *(__half2*)(g_V16 + (size_t)(m + 8) * D_ + n) = v23;
            }
        }
}

// ---------------- GEMM 2: S = Q' @ x^T (compact triangular grid) ----------
__global__ __launch_bounds__(256, 2) void qk_mm()
{
    const int i = blockIdx.x, bt = blockIdx.z;
    int qt = (int)((sqrtf(8.0f * i + 1.0f) - 1.0f) * 0.5f);
    while ((qt + 1) * (qt + 2) / 2 <= i) qt++;
    while (qt * (qt + 1) / 2 > i) qt--;
    const int kt = i - qt * (qt + 1) / 2;

    extern __shared__ char smem[];
    float acc[2][8][4] = {};

    const size_t rb = (size_t)bt * N_ * D_;
    mainloop<false>(g_Qh + rb + (size_t)qt * 128 * D_, g_Ql + rb + (size_t)qt * 128 * D_, D_,
                    g_xh + rb + (size_t)kt * 128 * D_, g_xl + rb + (size_t)kt * 128 * D_, D_,
                    D_ / 32, smem, acc);

    float* S = g_S + (size_t)bt * N_ * N_;
    const int lane = threadIdx.x & 31, w = threadIdx.x >> 5;
    const int m0w = (w & 3) * 32, n0w = (w >> 2) * 64;
#pragma unroll
    for (int mt = 0; mt < 2; mt++)
#pragma unroll
        for (int nt = 0; nt < 8; nt++) {
            int q = qt * 128 + m0w + mt * 16 + (lane >> 2);
            int n = kt * 128 + n0w + nt * 8 + (lane & 3) * 2;
            float* c = acc[mt][nt];
            *(float2*)(S + (size_t)q * N_ + n)       = make_float2(c[0], c[1]);
            *(float2*)(S + (size_t)(q + 8) * N_ + n) = make_float2(c[2], c[3]);
        }
}

// ---------------- softmax -> P single fp16 (zero-padded to tile) ----------
__global__ __launch_bounds__(256) void softmax_k()
{
    const int row = blockIdx.x;
    const int bt = row >> 11;
    const int q  = row & (N_ - 1);
    const size_t base = (size_t)bt * N_ * N_ + (size_t)q * N_;
    const float* S = g_S + base;
    const int L = q + 1;
    const int tid = threadIdx.x;
    const float scale = 0.03125f;

    float pv[8];
    float m = -3.4e38f;
#pragma unroll
    for (int kk = 0; kk < 8; kk++) {
        int i = tid + kk * 256;
        pv[kk] = (i < L) ? S[i] : -3.4e38f;
        m = fmaxf(m, pv[kk]);
    }
#pragma unroll
    for (int off = 16; off; off >>= 1) m = fmaxf(m, __shfl_xor_sync(~0u, m, off));
    __shared__ float red[8];
    if ((tid & 31) == 0) red[tid >> 5] = m;
    __syncthreads();
    float mall = red[0];
#pragma unroll
    for (int j = 1; j < 8; j++) mall = fmaxf(mall, red[j]);
    __syncthreads();

    float sum = 0.f;
#pragma unroll
    for (int kk = 0; kk < 8; kk++) {
        int i = tid + kk * 256;
        if (i < L) { pv[kk] = expf((pv[kk] - mall) * scale); sum += pv[kk]; }
    }
#pragma unroll
    for (int off = 16; off; off >>= 1) sum += __shfl_xor_sync(~0u, sum, off);
    if ((tid & 31) == 0) red[tid >> 5] = sum;
    __syncthreads();
    float tot = 0.f;
#pragma unroll
    for (int j = 0; j < 8; j++) tot += red[j];
    const float inv = 1.0f / tot;

    const int Lpad = ((q >> 7) + 1) << 7;
#pragma unroll
    for (int kk = 0; kk < 8; kk++) {
        int i = tid + kk * 256;
        if (i < Lpad) {
            float p = (i < L) ? pv[kk] * inv : 0.f;
            g_P16[base + i] = __float2half(p);
        }
    }
}

// ---------------- GEMM 3: out = P @ V (fp16 single-limb, 1 MMA) ----------
__global__ __launch_bounds__(256, 2) void pv_mm(float* __restrict__ out)
{
    const int et = blockIdx.x, qt = (N_ / 128 - 1) - blockIdx.y, bt = blockIdx.z;
    extern __shared__ char smem[];
    float acc[2][8][4] = {};

    const size_t pb = (size_t)bt * N_ * N_ + (size_t)(qt * 128) * N_;
    const size_t vb = (size_t)bt * N_ * D_ + et * 128;
    mainloop_h1(g_P16 + pb, N_,
                g_V16 + vb, D_,
                (qt + 1) * 4, smem, acc);

    const int lane = threadIdx.x & 31, w = threadIdx.x >> 5;
    const int m0w = (w & 3) * 32, n0w = (w >> 2) * 64;
#pragma unroll
    for (int mt = 0; mt < 2; mt++)
#pragma unroll
        for (int nt = 0; nt < 8; nt++) {
            int q = qt * 128 + m0w + mt * 16 + (lane >> 2);
            int n = et * 128 + n0w + nt * 8 + (lane & 3) * 2;
            float* c = acc[mt][nt];
            float* O = out + ((size_t)bt * N_ + q) * D_ + n;
            *(float2*)O            = make_float2(c[0], c[1]);
            *(float2*)(O + 8 * D_) = make_float2(c[2], c[3]);
        }
}

// ---------------------------------------------------------------------------
extern "C" void kernel_launch(void* const* d_in, const int* in_sizes, int n_in,
                              void* d_out, int out_size)
{
    const float* x  = (const float*)d_in[0];
    const float* Wq = (const float*)d_in[1];
    const float* Wk = (const float*)d_in[2];
    const float* Wv = (const float*)d_in[3];
    float* out = (float*)d_out;

    cudaFuncSetAttribute(wqk_mm, cudaFuncAttributeMaxDynamicSharedMemorySize, SM_TOTAL);
    cudaFuncSetAttribute(qv_mm,  cudaFuncAttributeMaxDynamicSharedMemorySize, SM_TOTAL);
    cudaFuncSetAttribute(qk_mm,  cudaFuncAttributeMaxDynamicSharedMemorySize, SM_TOTAL);
    cudaFuncSetAttribute(pv_mm,  cudaFuncAttributeMaxDynamicSharedMemorySize, SM_PV);

    const int NT = N_ / 128;                       // 16
    const int NTRI = NT * (NT + 1) / 2;            // 136

    dim3 blk(256);
    convert_x<<<M_TOT * D_ / 4 / 256, blk>>>(x);
    convert_w<<<dim3(D_ * D_ / 4 / 256, 1, 3), blk>>>(Wq, Wk, Wv);
    wqk_mm<<<dim3(8, 8), blk, SM_TOTAL>>>();
    qv_mm<<<dim3(D_ / 128, M_TOT / 128, 2), blk, SM_TOTAL>>>();
    qk_mm<<<dim3(NTRI, 1, B_), blk, SM_TOTAL>>>();
    softmax_k<<<M_TOT, blk>>>();
    pv_mm<<<dim3(D_ / 128, NT, B_), blk, SM_PV>>>(out);
}

// round 17
// speedup vs baseline: 1.8092x; 1.2922x over previous
#include <cuda_runtime.h>
#include <cuda_bf16.h>
#include <cuda_fp16.h>
#include <cstdint>

#define B_ 4
#define N_ 2048
#define D_ 1024
#define M_TOT (B_ * N_)

typedef __nv_bfloat16 bf16;

// ---------------- static device scratch ----------------
__device__ __align__(16) __half g_x16[M_TOT * D_];                  // x single fp16
__device__ __align__(16) bf16  g_Wh[2 * D_ * D_], g_Wl[2 * D_ * D_]; // Wq, Wk bf16 splits (wqk)
__device__ __align__(16) __half g_Wv16h[D_ * D_], g_Wv16l[D_ * D_];  // Wv fp16 limbs
__device__ __align__(16) __half g_M16h[D_ * D_],  g_M16l[D_ * D_];   // M = Wq Wk^T fp16 limbs
__device__ __align__(16) __half g_Q16h[M_TOT * D_], g_Q16l[M_TOT * D_]; // Q' fp16 limbs
__device__ __align__(16) __half g_V16[M_TOT * D_];                  // V single fp16
__device__ __align__(16) float g_S [(size_t)B_ * N_ * N_];
__device__ __align__(16) __half g_P16[(size_t)B_ * N_ * N_];        // P single fp16

// ---------------- smem ----------------
static constexpr int ARR = 8192;
// bf16 wqk: 4 arrays/stage
static constexpr int STAGE4 = 4 * ARR;
static constexpr int SM_W = 3 * STAGE4;      // 98304
// qv/qk: 3 arrays/stage
static constexpr int STAGE3 = 3 * ARR;
static constexpr int SM_3 = 3 * STAGE3;      // 73728
// pv: 2 arrays/stage
static constexpr int STAGE2 = 2 * ARR;
static constexpr int SM_PV = 3 * STAGE2;     // 49152

__device__ __forceinline__ uint32_t swzN(uint32_t r, uint32_t c) {   // 64B rows
    return r * 64u + (c ^ ((r & 6u) << 3));
}
__device__ __forceinline__ uint32_t swzT(uint32_t r, uint32_t c) {   // 256B rows
    return r * 256u + (c ^ ((r & 7u) << 4));
}

// ---------------- PTX helpers ----------------
__device__ __forceinline__ uint32_t smem_u32(const void* p) {
    uint32_t a;
    asm("{ .reg .u64 t; cvta.to.shared.u64 t, %1; cvt.u32.u64 %0, t; }" : "=r"(a) : "l"(p));
    return a;
}
__device__ __forceinline__ void cp16(uint32_t dst, const void* src) {
    asm volatile("cp.async.cg.shared.global [%0], [%1], 16;" :: "r"(dst), "l"(src));
}
__device__ __forceinline__ void cp_commit() { asm volatile("cp.async.commit_group;"); }
__device__ __forceinline__ void cp_wait1()  { asm volatile("cp.async.wait_group 1;"); }

__device__ __forceinline__ void ldsm_x4(uint32_t r[4], uint32_t addr) {
    asm volatile("ldmatrix.sync.aligned.m8n8.x4.shared.b16 {%0,%1,%2,%3}, [%4];"
                 : "=r"(r[0]), "=r"(r[1]), "=r"(r[2]), "=r"(r[3]) : "r"(addr));
}
__device__ __forceinline__ void ldsm_x4_t(uint32_t r[4], uint32_t addr) {
    asm volatile("ldmatrix.sync.aligned.m8n8.x4.trans.shared.b16 {%0,%1,%2,%3}, [%4];"
                 : "=r"(r[0]), "=r"(r[1]), "=r"(r[2]), "=r"(r[3]) : "r"(addr));
}
__device__ __forceinline__ void mma16816(float c[4], const uint32_t a[4], uint32_t b0, uint32_t b1) {
    asm volatile("mma.sync.aligned.m16n8k16.row.col.f32.bf16.bf16.f32 "
                 "{%0,%1,%2,%3}, {%4,%5,%6,%7}, {%8,%9}, {%0,%1,%2,%3};"
                 : "+f"(c[0]), "+f"(c[1]), "+f"(c[2]), "+f"(c[3])
                 : "r"(a[0]), "r"(a[1]), "r"(a[2]), "r"(a[3]), "r"(b0), "r"(b1));
}
__device__ __forceinline__ void mma16816h(float c[4], const uint32_t a[4], uint32_t b0, uint32_t b1) {
    asm volatile("mma.sync.aligned.m16n8k16.row.col.f32.f16.f16.f32 "
                 "{%0,%1,%2,%3}, {%4,%5,%6,%7}, {%8,%9}, {%0,%1,%2,%3};"
                 : "+f"(c[0]), "+f"(c[1]), "+f"(c[2]), "+f"(c[3])
                 : "r"(a[0]), "r"(a[1]), "r"(a[2]), "r"(a[3]), "r"(b0), "r"(b1));
}

__device__ __forceinline__ unsigned pack2(bf16 a, bf16 b) {
    __nv_bfloat162 t(a, b);
    return *reinterpret_cast<unsigned*>(&t);
}
__device__ __forceinline__ unsigned pack2h(__half a, __half b) {
    __half2 t(a, b);
    return *reinterpret_cast<unsigned*>(&t);
}
__device__ __forceinline__ void split1(float v, bf16& h, bf16& l) {
    h = __float2bfloat16(v);
    l = __float2bfloat16(v - __bfloat162float(h));
}
__device__ __forceinline__ void split1h(float v, __half& h, __half& l) {
    h = __float2half(v);
    l = __float2half(v - __half2float(h));
}

// ---------------------------------------------------------------------------
// bf16 split mainloop (wqk only): B as [n][k] rows (TRANSB=false path of R11)
// ---------------------------------------------------------------------------
__device__ __forceinline__ void mainloop_bf3(
    const bf16* __restrict__ Ah, const bf16* __restrict__ Al, int lda,
    const bf16* __restrict__ Bh, const bf16* __restrict__ Bl, int ldb,
    int nch, char* smem, float (&acc)[2][8][4])
{
    const uint32_t su = smem_u32(smem);
    const int tid = threadIdx.x;
    const int lane = tid & 31, w = tid >> 5;
    const int m0w = (w & 3) * 32, n0w = (w >> 2) * 64;
    const int arow = tid >> 1;
    const int ac0  = (tid & 1) * 32;

    auto load_chunk = [&](int ch, int st) {
        const int k0 = ch * 32;
        const uint32_t base = su + st * STAGE4;
        const bf16* pAh = Ah + (size_t)arow * lda + k0 + (ac0 >> 1);
        const bf16* pAl = Al + (size_t)arow * lda + k0 + (ac0 >> 1);
        uint32_t d0 = base + swzN(arow, ac0);
        uint32_t d1 = base + swzN(arow, ac0 + 16);
        cp16(d0, pAh);            cp16(d1, pAh + 8);
        cp16(d0 + ARR, pAl);      cp16(d1 + ARR, pAl + 8);
        const bf16* pBh = Bh + (size_t)arow * ldb + k0 + (ac0 >> 1);
        const bf16* pBl = Bl + (size_t)arow * ldb + k0 + (ac0 >> 1);
        uint32_t e0 = base + 2 * ARR + swzN(arow, ac0);
        uint32_t e1 = base + 2 * ARR + swzN(arow, ac0 + 16);
        cp16(e0, pBh);        cp16(e1, pBh + 8);
        cp16(e0 + ARR, pBl);  cp16(e1 + ARR, pBl + 8);
    };

    load_chunk(0, 0); cp_commit();
    if (nch > 1) load_chunk(1, 1);
    cp_commit();

    for (int ch = 0; ch < nch; ch++) {
        cp_wait1();
        __syncthreads();
        if (ch + 2 < nch) load_chunk(ch + 2, (ch + 2) % 3);
        cp_commit();

        const uint32_t base = su + (ch % 3) * STAGE4;
#pragma unroll
        for (int kk = 0; kk < 2; kk++) {
            uint32_t Af[2][4], Alf[2][4];
            {
                const uint32_t r0 = m0w + (lane & 15);
                const uint32_t c0 = (lane >> 4) * 16 + kk * 32;
#pragma unroll
                for (int mt = 0; mt < 2; mt++) {
                    uint32_t a0 = base + swzN(r0 + mt * 16, c0);
                    ldsm_x4(Af[mt],  a0);
                    ldsm_x4(Alf[mt], a0 + ARR);
                }
            }
#pragma unroll
            for (int p = 0; p < 4; p++) {
                uint32_t q[4], ql[4];
                const uint32_t r0 = n0w + (lane & 7) + ((lane >> 4) << 3) + p * 16;
                const uint32_t c0 = ((lane >> 3) & 1) * 16 + kk * 32;
                uint32_t b0 = base + 2 * ARR + swzN(r0, c0);
                ldsm_x4(q,  b0);
                ldsm_x4(ql, b0 + ARR);
                const int nt0 = 2 * p, nt1 = 2 * p + 1;
                mma16816(acc[0][nt0], Af[0],  q[0],  q[1]);
                mma16816(acc[1][nt0], Af[1],  q[0],  q[1]);
                mma16816(acc[0][nt1], Af[0],  q[2],  q[3]);
                mma16816(acc[1][nt1], Af[1],  q[2],  q[3]);

                mma16816(acc[0][nt0], Af[0],  ql[0], ql[1]);
                mma16816(acc[1][nt0], Af[1],  ql[0], ql[1]);
                mma16816(acc[0][nt1], Af[0],  ql[2], ql[3]);
                mma16816(acc[1][nt1], Af[1],  ql[2], ql[3]);

                mma16816(acc[0][nt0], Alf[0], q[0],  q[1]);
                mma16816(acc[1][nt0], Alf[1], q[0],  q[1]);
                mma16816(acc[0][nt1], Alf[0], q[2],  q[3]);
                mma16816(acc[1][nt1], Alf[1], q[2],  q[3]);
            }
        }
    }
    __syncthreads();
}

// ---------------------------------------------------------------------------
// qv mainloop: A single fp16 [m][k] rows, B split fp16 [k][n] trans rows.
// 2 MMAs per (mt,nt).
// ---------------------------------------------------------------------------
__device__ __forceinline__ void mainloop_qv(
    const __half* __restrict__ A, int lda,
    const __half* __restrict__ Bh, const __half* __restrict__ Bl, int ldb,
    int nch, char* smem, float (&acc)[2][8][4])
{
    const uint32_t su = smem_u32(smem);
    const int tid = threadIdx.x;
    const int lane = tid & 31, w = tid >> 5;
    const int m0w = (w & 3) * 32, n0w = (w >> 2) * 64;
    const int arow = tid >> 1;
    const int ac0  = (tid & 1) * 32;
    const int tkr = tid >> 4, tseg = tid & 15;

    auto load_chunk = [&](int ch, int st) {
        const int k0 = ch * 32;
        const uint32_t base = su + st * STAGE3;
        const __half* pA = A + (size_t)arow * lda + k0 + (ac0 >> 1);
        cp16(base + swzN(arow, ac0),      pA);
        cp16(base + swzN(arow, ac0 + 16), pA + 8);
        const __half* pBh0 = Bh + (size_t)(k0 + tkr) * ldb + tseg * 8;
        const __half* pBh1 = Bh + (size_t)(k0 + tkr + 16) * ldb + tseg * 8;
        const __half* pBl0 = Bl + (size_t)(k0 + tkr) * ldb + tseg * 8;
        const __half* pBl1 = Bl + (size_t)(k0 + tkr + 16) * ldb + tseg * 8;
        cp16(base + ARR + swzT(tkr, tseg * 16),          pBh0);
        cp16(base + ARR + swzT(tkr + 16, tseg * 16),     pBh1);
        cp16(base + 2 * ARR + swzT(tkr, tseg * 16),      pBl0);
        cp16(base + 2 * ARR + swzT(tkr + 16, tseg * 16), pBl1);
    };

    load_chunk(0, 0); cp_commit();
    if (nch > 1) load_chunk(1, 1);
    cp_commit();

    for (int ch = 0; ch < nch; ch++) {
        cp_wait1();
        __syncthreads();
        if (ch + 2 < nch) load_chunk(ch + 2, (ch + 2) % 3);
        cp_commit();

        const uint32_t base = su + (ch % 3) * STAGE3;
#pragma unroll
        for (int kk = 0; kk < 2; kk++) {
            uint32_t Af[2][4];
            {
                const uint32_t r0 = m0w + (lane & 15);
                const uint32_t c0 = (lane >> 4) * 16 + kk * 32;
#pragma unroll
                for (int mt = 0; mt < 2; mt++)
                    ldsm_x4(Af[mt], base + swzN(r0 + mt * 16, c0));
            }
#pragma unroll
            for (int p = 0; p < 4; p++) {
                uint32_t qh[4], ql[4];
                const uint32_t r0 = (lane & 15) + kk * 16;
                const uint32_t c0 = (lane >> 4) * 16 + n0w * 2 + p * 32;
                ldsm_x4_t(qh, base + ARR + swzT(r0, c0));
                ldsm_x4_t(ql, base + 2 * ARR + swzT(r0, c0));
                const int nt0 = 2 * p, nt1 = 2 * p + 1;
                mma16816h(acc[0][nt0], Af[0], qh[0], qh[1]);
                mma16816h(acc[1][nt0], Af[1], qh[0], qh[1]);
                mma16816h(acc[0][nt1], Af[0], qh[2], qh[3]);
                mma16816h(acc[1][nt1], Af[1], qh[2], qh[3]);

                mma16816h(acc[0][nt0], Af[0], ql[0], ql[1]);
                mma16816h(acc[1][nt0], Af[1], ql[0], ql[1]);
                mma16816h(acc[0][nt1], Af[0], ql[2], ql[3]);
                mma16816h(acc[1][nt1], Af[1], ql[2], ql[3]);
            }
        }
    }
    __syncthreads();
}

// ---------------------------------------------------------------------------
// qk mainloop: A split fp16 [m][k] rows, B single fp16 [n][k] rows (normal).
// 2 MMAs per (mt,nt).
// ---------------------------------------------------------------------------
__device__ __forceinline__ void mainloop_qk(
    const __half* __restrict__ Ah, const __half* __restrict__ Al, int lda,
    const __half* __restrict__ B, int ldb,
    int nch, char* smem, float (&acc)[2][8][4])
{
    const uint32_t su = smem_u32(smem);
    const int tid = threadIdx.x;
    const int lane = tid & 31, w = tid >> 5;
    const int m0w = (w & 3) * 32, n0w = (w >> 2) * 64;
    const int arow = tid >> 1;
    const int ac0  = (tid & 1) * 32;

    auto load_chunk = [&](int ch, int st) {
        const int k0 = ch * 32;
        const uint32_t base = su + st * STAGE3;
        const __half* pAh = Ah + (size_t)arow * lda + k0 + (ac0 >> 1);
        const __half* pAl = Al + (size_t)arow * lda + k0 + (ac0 >> 1);
        uint32_t d0 = base + swzN(arow, ac0);
        uint32_t d1 = base + swzN(arow, ac0 + 16);
        cp16(d0, pAh);            cp16(d1, pAh + 8);
        cp16(d0 + ARR, pAl);      cp16(d1 + ARR, pAl + 8);
        const __half* pB = B + (size_t)arow * ldb + k0 + (ac0 >> 1);
        cp16(base + 2 * ARR + swzN(arow, ac0),      pB);
        cp16(base + 2 * ARR + swzN(arow, ac0 + 16), pB + 8);
    };

    load_chunk(0, 0); cp_commit();
    if (nch > 1) load_chunk(1, 1);
    cp_commit();

    for (int ch = 0; ch < nch; ch++) {
        cp_wait1();
        __syncthreads();
        if (ch + 2 < nch) load_chunk(ch + 2, (ch + 2) % 3);
        cp_commit();

        const uint32_t base = su + (ch % 3) * STAGE3;
#pragma unroll
        for (int kk = 0; kk < 2; kk++) {
            uint32_t Afh[2][4], Afl[2][4];
            {
                const uint32_t r0 = m0w + (lane & 15);
                const uint32_t c0 = (lane >> 4) * 16 + kk * 32;
#pragma unroll
                for (int mt = 0; mt < 2; mt++) {
                    uint32_t a0 = base + swzN(r0 + mt * 16, c0);
                    ldsm_x4(Afh[mt], a0);
                    ldsm_x4(Afl[mt], a0 + ARR);
                }
            }
#pragma unroll
            for (int p = 0; p < 4; p++) {
                uint32_t q[4];
                const uint32_t r0 = n0w + (lane & 7) + ((lane >> 4) << 3) + p * 16;
                const uint32_t c0 = ((lane >> 3) & 1) * 16 + kk * 32;
                ldsm_x4(q, base + 2 * ARR + swzN(r0, c0));
                const int nt0 = 2 * p, nt1 = 2 * p + 1;
                mma16816h(acc[0][nt0], Afh[0], q[0], q[1]);
                mma16816h(acc[1][nt0], Afh[1], q[0], q[1]);
                mma16816h(acc[0][nt1], Afh[0], q[2], q[3]);
                mma16816h(acc[1][nt1], Afh[1], q[2], q[3]);

                mma16816h(acc[0][nt0], Afl[0], q[0], q[1]);
                mma16816h(acc[1][nt0], Afl[1], q[0], q[1]);
                mma16816h(acc[0][nt1], Afl[0], q[2], q[3]);
                mma16816h(acc[1][nt1], Afl[1], q[2], q[3]);
            }
        }
    }
    __syncthreads();
}

// ---------------------------------------------------------------------------
// pv mainloop (R16 proven): A single fp16 normal, B single fp16 trans. 1 MMA.
// ---------------------------------------------------------------------------
__device__ __forceinline__ void mainloop_h1(
    const __half* __restrict__ A, int lda,
    const __half* __restrict__ Bt, int ldb,
    int nch, char* smem, float (&acc)[2][8][4])
{
    const uint32_t su = smem_u32(smem);
    const int tid = threadIdx.x;
    const int lane = tid & 31, w = tid >> 5;
    const int m0w = (w & 3) * 32, n0w = (w >> 2) * 64;
    const int arow = tid >> 1;
    const int ac0  = (tid & 1) * 32;
    const int tkr = tid >> 4, tseg = tid & 15;

    auto load_chunk = [&](int ch, int st) {
        const int k0 = ch * 32;
        const uint32_t base = su + st * STAGE2;
        const __half* pA = A + (size_t)arow * lda + k0 + (ac0 >> 1);
        cp16(base + swzN(arow, ac0),      pA);
        cp16(base + swzN(arow, ac0 + 16), pA + 8);
        const __half* pB0 = Bt + (size_t)(k0 + tkr) * ldb + tseg * 8;
        const __half* pB1 = Bt + (size_t)(k0 + tkr + 16) * ldb + tseg * 8;
        cp16(base + ARR + swzT(tkr, tseg * 16),      pB0);
        cp16(base + ARR + swzT(tkr + 16, tseg * 16), pB1);
    };

    load_chunk(0, 0); cp_commit();
    if (nch > 1) load_chunk(1, 1);
    cp_commit();

    for (int ch = 0; ch < nch; ch++) {
        cp_wait1();
        __syncthreads();
        if (ch + 2 < nch) load_chunk(ch + 2, (ch + 2) % 3);
        cp_commit();

        const uint32_t base = su + (ch % 3) * STAGE2;
#pragma unroll
        for (int kk = 0; kk < 2; kk++) {
            uint32_t Af[2][4];
            {
                const uint32_t r0 = m0w + (lane & 15);
                const uint32_t c0 = (lane >> 4) * 16 + kk * 32;
#pragma unroll
                for (int mt = 0; mt < 2; mt++)
                    ldsm_x4(Af[mt], base + swzN(r0 + mt * 16, c0));
            }
#pragma unroll
            for (int p = 0; p < 4; p++) {
                uint32_t q[4];
                const uint32_t r0 = (lane & 15) + kk * 16;
                const uint32_t c0 = (lane >> 4) * 16 + n0w * 2 + p * 32;
                ldsm_x4_t(q, base + ARR + swzT(r0, c0));
                const int nt0 = 2 * p, nt1 = 2 * p + 1;
                mma16816h(acc[0][nt0], Af[0], q[0], q[1]);
                mma16816h(acc[1][nt0], Af[1], q[0], q[1]);
                mma16816h(acc[0][nt1], Af[0], q[2], q[3]);
                mma16816h(acc[1][nt1], Af[1], q[2], q[3]);
            }
        }
    }
    __syncthreads();
}

// ---------------- precompute ----------------
__global__ __launch_bounds__(256) void convert_x(const float* __restrict__ x)
{
    size_t idx = (size_t)(blockIdx.x * 256 + threadIdx.x) * 4;
    float4 v = *(const float4*)(x + idx);
    unsigned u0 = pack2h(__float2half(v.x), __float2half(v.y));
    unsigned u1 = pack2h(__float2half(v.z), __float2half(v.w));
    *(uint2*)(g_x16 + idx) = make_uint2(u0, u1);
}

__global__ __launch_bounds__(256) void convert_w(
    const float* __restrict__ Wq, const float* __restrict__ Wk, const float* __restrict__ Wv)
{
    const int z = blockIdx.z;
    const float* W = (z == 0) ? Wq : (z == 1) ? Wk : Wv;
    size_t idx = (size_t)(blockIdx.x * 256 + threadIdx.x) * 4;
    float4 v = *(const float4*)(W + idx);
    if (z < 2) {
        size_t base = (size_t)z * D_ * D_;
        bf16 h[4], l[4];
        split1(v.x, h[0], l[0]); split1(v.y, h[1], l[1]);
        split1(v.z, h[2], l[2]); split1(v.w, h[3], l[3]);
        *(uint2*)(g_Wh + base + idx) = make_uint2(pack2(h[0], h[1]), pack2(h[2], h[3]));
        *(uint2*)(g_Wl + base + idx) = make_uint2(pack2(l[0], l[1]), pack2(l[2], l[3]));
    } else {
        __half h[4], l[4];
        split1h(v.x, h[0], l[0]); split1h(v.y, h[1], l[1]);
        split1h(v.z, h[2], l[2]); split1h(v.w, h[3], l[3]);
        *(uint2*)(g_Wv16h + idx) = make_uint2(pack2h(h[0], h[1]), pack2h(h[2], h[3]));
        *(uint2*)(g_Wv16l + idx) = make_uint2(pack2h(l[0], l[1]), pack2h(l[2], l[3]));
    }
}

// ---------------- GEMM 0: M = Wq @ Wk^T (bf16 3-term) -> fp16 limbs -------
__global__ __launch_bounds__(256, 2) void wqk_mm()
{
    extern __shared__ char smem[];
    const int n0 = blockIdx.x * 128, m0 = blockIdx.y * 128;
    float acc[2][8][4] = {};

    mainloop_bf3(g_Wh + (size_t)m0 * D_, g_Wl + (size_t)m0 * D_, D_,
                 g_Wh + (size_t)D_ * D_ + (size_t)n0 * D_,
                 g_Wl + (size_t)D_ * D_ + (size_t)n0 * D_, D_,
                 D_ / 32, smem, acc);

    const int lane = threadIdx.x & 31, w = threadIdx.x >> 5;
    const int m0w = (w & 3) * 32, n0w = (w >> 2) * 64;
#pragma unroll
    for (int mt = 0; mt < 2; mt++)
#pragma unroll
        for (int nt = 0; nt < 8; nt++) {
            int m = m0 + m0w + mt * 16 + (lane >> 2);   // d1
            int n = n0 + n0w + nt * 8 + (lane & 3) * 2; // d2
            float* c = acc[mt][nt];
            __half h0, l0, h1, l1;
            split1h(c[0], h0, l0); split1h(c[1], h1, l1);
            *(unsigned*)(g_M16h + (size_t)m * D_ + n) = pack2h(h0, h1);
            *(unsigned*)(g_M16l + (size_t)m * D_ + n) = pack2h(l0, l1);
            split1h(c[2], h0, l0); split1h(c[3], h1, l1);
            *(unsigned*)(g_M16h + (size_t)(m + 8) * D_ + n) = pack2h(h0, h1);
            *(unsigned*)(g_M16l + (size_t)(m + 8) * D_ + n) = pack2h(l0, l1);
        }
}

// ---------------- GEMM 1: Q' = x @ M (z=0), V = x @ Wv (z=1) --------------
__global__ __launch_bounds__(256, 2) void qv_mm()
{
    extern __shared__ char smem[];
    const int n0 = blockIdx.x * 128, m0 = blockIdx.y * 128, z = blockIdx.z;
    float acc[2][8][4] = {};

    const __half* Bh = (z == 0) ? g_M16h : g_Wv16h;
    const __half* Bl = (z == 0) ? g_M16l : g_Wv16l;
    mainloop_qv(g_x16 + (size_t)m0 * D_, D_,
                Bh + n0, Bl + n0, D_,
                D_ / 32, smem, acc);

    const int lane = threadIdx.x & 31, w = threadIdx.x >> 5;
    const int m0w = (w & 3) * 32, n0w = (w >> 2) * 64;
#pragma unroll
    for (int mt = 0; mt < 2; mt++)
#pragma unroll
        for (int nt = 0; nt < 8; nt++) {
            int m = m0 + m0w + mt * 16 + (lane >> 2);
            int n = n0 + n0w + nt * 8 + (lane & 3) * 2;
            float* c = acc[mt][nt];
            if (z == 0) {
                __half h0, l0, h1, l1;
                split1h(c[0], h0, l0); split1h(c[1], h1, l1);
                *(unsigned*)(g_Q16h + (size_t)m * D_ + n) = pack2h(h0, h1);
                *(unsigned*)(g_Q16l + (size_t)m * D_ + n) = pack2h(l0, l1);
                split1h(c[2], h0, l0); split1h(c[3], h1, l1);
                *(unsigned*)(g_Q16h + (size_t)(m + 8) * D_ + n) = pack2h(h0, h1);
                *(unsigned*)(g_Q16l + (size_t)(m + 8) * D_ + n) = pack2h(l0, l1);
            } else {
                *(unsigned*)(g_V16 + (size_t)m * D_ + n) =
                    pack2h(__float2half(c[0]), __float2half(c[1]));
                *(unsigned*)(g_V16 + (size_t)(m + 8) * D_ + n) =
                    pack2h(__float2half(c[2]), __float2half(c[3]));
            }
        }
}

// ---------------- GEMM 2: S = Q' @ x^T (compact triangular grid) ----------
__global__ __launch_bounds__(256, 2) void qk_mm()
{
    const int i = blockIdx.x, bt = blockIdx.z;
    int qt = (int)((sqrtf(8.0f * i + 1.0f) - 1.0f) * 0.5f);
    while ((qt + 1) * (qt + 2) / 2 <= i) qt++;
    while (qt * (qt + 1) / 2 > i) qt--;
    const int kt = i - qt * (qt + 1) / 2;

    extern __shared__ char smem[];
    float acc[2][8][4] = {};

    const size_t rb = (size_t)bt * N_ * D_;
    mainloop_qk(g_Q16h + rb + (size_t)qt * 128 * D_,
                g_Q16l + rb + (size_t)qt * 128 * D_, D_,
                g_x16 + rb + (size_t)kt * 128 * D_, D_,
                D_ / 32, smem, acc);

    float* S = g_S + (size_t)bt * N_ * N_;
    const int lane = threadIdx.x & 31, w = threadIdx.x >> 5;
    const int m0w = (w & 3) * 32, n0w = (w >> 2) * 64;
#pragma unroll
    for (int mt = 0; mt < 2; mt++)
#pragma unroll
        for (int nt = 0; nt < 8; nt++) {
            int q = qt * 128 + m0w + mt * 16 + (lane >> 2);
            int n = kt * 128 + n0w + nt * 8 + (lane & 3) * 2;
            float* c = acc[mt][nt];
            *(float2*)(S + (size_t)q * N_ + n)       = make_float2(c[0], c[1]);
            *(float2*)(S + (size_t)(q + 8) * N_ + n) = make_float2(c[2], c[3]);
        }
}

// ---------------- softmax -> P single fp16 (zero-padded to tile) ----------
__global__ __launch_bounds__(256) void softmax_k()
{
    const int row = blockIdx.x;
    const int bt = row >> 11;
    const int q  = row & (N_ - 1);
    const size_t base = (size_t)bt * N_ * N_ + (size_t)q * N_;
    const float* S = g_S + base;
    const int L = q + 1;
    const int tid = threadIdx.x;
    const float scale = 0.03125f;

    float pv[8];
    float m = -3.4e38f;
#pragma unroll
    for (int kk = 0; kk < 8; kk++) {
        int i = tid + kk * 256;
        pv[kk] = (i < L) ? S[i] : -3.4e38f;
        m = fmaxf(m, pv[kk]);
    }
#pragma unroll
    for (int off = 16; off; off >>= 1) m = fmaxf(m, __shfl_xor_sync(~0u, m, off));
    __shared__ float red[8];
    if ((tid & 31) == 0) red[tid >> 5] = m;
    __syncthreads();
    float mall = red[0];
#pragma unroll
    for (int j = 1; j < 8; j++) mall = fmaxf(mall, red[j]);
    __syncthreads();

    float sum = 0.f;
#pragma unroll
    for (int kk = 0; kk < 8; kk++) {
        int i = tid + kk * 256;
        if (i < L) { pv[kk] = expf((pv[kk] - mall) * scale); sum += pv[kk]; }
    }
#pragma unroll
    for (int off = 16; off; off >>= 1) sum += __shfl_xor_sync(~0u, sum, off);
    if ((tid & 31) == 0) red[tid >> 5] = sum;
    __syncthreads();
    float tot = 0.f;
#pragma unroll
    for (int j = 0; j < 8; j++) tot += red[j];
    const float inv = 1.0f / tot;

    const int Lpad = ((q >> 7) + 1) << 7;
#pragma unroll
    for (int kk = 0; kk < 8; kk++) {
        int i = tid + kk * 256;
        if (i < Lpad) {
            float p = (i < L) ? pv[kk] * inv : 0.f;
            g_P16[base + i] = __float2half(p);
        }
    }
}

// ---------------- GEMM 3: out = P @ V (fp16 single, 1 MMA) ----------------
__global__ __launch_bounds__(256, 2) void pv_mm(float* __restrict__ out)
{
    const int et = blockIdx.x, qt = (N_ / 128 - 1) - blockIdx.y, bt = blockIdx.z;
    extern __shared__ char smem[];
    float acc[2][8][4] = {};

    const size_t pb = (size_t)bt * N_ * N_ + (size_t)(qt * 128) * N_;
    const size_t vb = (size_t)bt * N_ * D_ + et * 128;
    mainloop_h1(g_P16 + pb, N_,
                g_V16 + vb, D_,
                (qt + 1) * 4, smem, acc);

    const int lane = threadIdx.x & 31, w = threadIdx.x >> 5;
    const int m0w = (w & 3) * 32, n0w = (w >> 2) * 64;
#pragma unroll
    for (int mt = 0; mt < 2; mt++)
#pragma unroll
        for (int nt = 0; nt < 8; nt++) {
            int q = qt * 128 + m0w + mt * 16 + (lane >> 2);
            int n = et * 128 + n0w + nt * 8 + (lane & 3) * 2;
            float* c = acc[mt][nt];
            float* O = out + ((size_t)bt * N_ + q) * D_ + n;
            *(float2*)O            = make_float2(c[0], c[1]);
            *(float2*)(O + 8 * D_) = make_float2(c[2], c[3]);
        }
}

// ---------------------------------------------------------------------------
extern "C" void kernel_launch(void* const* d_in, const int* in_sizes, int n_in,
                              void* d_out, int out_size)
{
    const float* x  = (const float*)d_in[0];
    const float* Wq = (const float*)d_in[1];
    const float* Wk = (const float*)d_in[2];
    const float* Wv = (const float*)d_in[3];
    float* out = (float*)d_out;

    cudaFuncSetAttribute(wqk_mm, cudaFuncAttributeMaxDynamicSharedMemorySize, SM_W);
    cudaFuncSetAttribute(qv_mm,  cudaFuncAttributeMaxDynamicSharedMemorySize, SM_3);
    cudaFuncSetAttribute(qk_mm,  cudaFuncAttributeMaxDynamicSharedMemorySize, SM_3);
    cudaFuncSetAttribute(pv_mm,  cudaFuncAttributeMaxDynamicSharedMemorySize, SM_PV);

    const int NT = N_ / 128;                       // 16
    const int NTRI = NT * (NT + 1) / 2;            // 136

    dim3 blk(256);
    convert_x<<<M_TOT * D_ / 4 / 256, blk>>>(x);
    convert_w<<<dim3(D_ * D_ / 4 / 256, 1, 3), blk>>>(Wq, Wk, Wv);
    wqk_mm<<<dim3(8, 8), blk, SM_W>>>();
    qv_mm<<<dim3(D_ / 128, M_TOT / 128, 2), blk, SM_3>>>();
    qk_mm<<<dim3(NTRI, 1, B_), blk, SM_3>>>();
    softmax_k<<<M_TOT, blk>>>();
    pv_mm<<<dim3(D_ / 128, NT, B_), blk, SM_PV>>>(out);
}